// round 1
// baseline (speedup 1.0000x reference)
#include <cuda_runtime.h>
#include <math.h>

// Problem constants (dataset-fixed: T=8, N=2048, E=256, H=768, D=16, n_predict=12)
#define NB    2048
#define DD    16
#define EE    256
#define HH    768
#define G3    2304        // 3*H
#define TT    8
#define NPRED 12
#define SCALEF 4.0f

// ---------------- device scratch (no allocations allowed) ----------------
__device__ float g_M1[DD*G3];
__device__ float g_M2[DD*G3];
__device__ float g_Md[DD*G3];
__device__ float g_b1[G3];
__device__ float g_b2[G3];
__device__ float g_bd[G3];
__device__ float g_W1T[HH*G3];   // e1_Whh^T   (768 x 2304)
__device__ float g_W2T[HH*G3];   // e2_Whh^T
__device__ float g_WdT[HH*G3];   // dec_Whh^T
__device__ float g_W2hT[HH*G3];  // e2_Wih[:,256:]^T
__device__ float g_C2[NB*G3];    // h_inv @ e2_Wih[:,256:]^T (constant across enc2 steps)
__device__ float g_G[NB*G3];     // gh buffer
__device__ float g_h[NB*HH];
__device__ float g_hinv[NB*HH];
__device__ float g_v[NB*DD];

// ---------------- tiny utility kernels ----------------
__global__ void zero_kernel(float* p, int n) {
    int i = blockIdx.x * blockDim.x + threadIdx.x;
    if (i < n) p[i] = 0.0f;
}

__global__ void copy_kernel(float* dst, const float* src, int n) {
    int i = blockIdx.x * blockDim.x + threadIdx.x;
    if (i < n) dst[i] = src[i];
}

__global__ void sub_kernel(const float* __restrict__ a, const float* __restrict__ b,
                           float* __restrict__ v, int n) {
    int i = blockIdx.x * blockDim.x + threadIdx.x;
    if (i < n) v[i] = a[i] - b[i];
}

// Fold embed() into Wih:  M[d][j] = SCALE * sum_e embW[e][d] * Wih[j][e]
//                         b[j]    = bih[j] + sum_e embB[e]  * Wih[j][e]
// (for enc2 only the first 256 columns of Wih are the embed part)
__global__ void prep_combined(const float* __restrict__ Wih, int ldw,
                              const float* __restrict__ bih,
                              const float* __restrict__ embW,
                              const float* __restrict__ embB,
                              float* __restrict__ Mout, float* __restrict__ bout) {
    int j = blockIdx.x * blockDim.x + threadIdx.x;
    if (j >= G3) return;
    float accM[DD];
    #pragma unroll
    for (int d = 0; d < DD; d++) accM[d] = 0.0f;
    float accb = 0.0f;
    const float* wrow = Wih + (size_t)j * ldw;
    for (int e = 0; e < EE; e++) {
        float w = wrow[e];
        accb += embB[e] * w;
        const float* er = embW + e * DD;
        #pragma unroll
        for (int d = 0; d < DD; d++) accM[d] += er[d] * w;
    }
    #pragma unroll
    for (int d = 0; d < DD; d++) Mout[d * G3 + j] = SCALEF * accM[d];
    bout[j] = accb + bih[j];
}

// Transpose a (G3 x ld) matrix column slice [off, off+HH) -> out (HH x G3)
__global__ void transpose_sub(const float* __restrict__ in, int ld, int off,
                              float* __restrict__ out) {
    __shared__ float tile[32][33];
    int jBase = blockIdx.x * 32;   // over G3 (rows of in)
    int kBase = blockIdx.y * 32;   // over HH (cols of in)
    int tx = threadIdx.x, ty = threadIdx.y;
    #pragma unroll
    for (int i = 0; i < 4; i++) {
        int jr = jBase + ty + i * 8;
        tile[ty + i * 8][tx] = in[(size_t)jr * ld + off + kBase + tx];
    }
    __syncthreads();
    #pragma unroll
    for (int i = 0; i < 4; i++) {
        int kr = kBase + ty + i * 8;
        out[(size_t)kr * G3 + jBase + tx] = tile[tx][ty + i * 8];
    }
}

// ---------------- main SGEMM: C(2048x2304) = A(2048x768) @ B(768x2304) ----------------
#define BM 128
#define BN 128
#define BK 16
#define TM 8
#define TN 8

__global__ __launch_bounds__(256)
void sgemm_kernel(const float* __restrict__ A, const float* __restrict__ B,
                  float* __restrict__ C) {
    __shared__ float As[BK][BM];
    __shared__ float Bs[BK][BN];

    int tid = threadIdx.x;
    int ty = tid >> 4;        // 0..15
    int tx = tid & 15;        // 0..15

    const float* Ab = A + (size_t)blockIdx.y * BM * HH;
    const float* Bb = B + (size_t)blockIdx.x * BN;

    float acc[TM][TN];
    #pragma unroll
    for (int i = 0; i < TM; i++)
        #pragma unroll
        for (int j = 0; j < TN; j++) acc[i][j] = 0.0f;

    for (int kt = 0; kt < HH; kt += BK) {
        // load A tile (128 x 16), transposed into As[k][m]
        #pragma unroll
        for (int i = 0; i < 2; i++) {
            int idx = tid + i * 256;
            int r  = idx >> 2;
            int k4 = (idx & 3) << 2;
            float4 av = *(const float4*)(Ab + (size_t)r * HH + kt + k4);
            As[k4 + 0][r] = av.x;
            As[k4 + 1][r] = av.y;
            As[k4 + 2][r] = av.z;
            As[k4 + 3][r] = av.w;
        }
        // load B tile (16 x 128)
        #pragma unroll
        for (int i = 0; i < 2; i++) {
            int idx = tid + i * 256;
            int kr = idx >> 5;
            int c4 = idx & 31;
            *(float4*)(&Bs[kr][c4 * 4]) =
                *(const float4*)(Bb + (size_t)(kt + kr) * G3 + c4 * 4);
        }
        __syncthreads();

        #pragma unroll
        for (int k = 0; k < BK; k++) {
            float ar[TM], br[TN];
            float4 a0 = *(const float4*)(&As[k][ty * TM]);
            float4 a1 = *(const float4*)(&As[k][ty * TM + 4]);
            ar[0]=a0.x; ar[1]=a0.y; ar[2]=a0.z; ar[3]=a0.w;
            ar[4]=a1.x; ar[5]=a1.y; ar[6]=a1.z; ar[7]=a1.w;
            float4 b0 = *(const float4*)(&Bs[k][tx * TN]);
            float4 b1 = *(const float4*)(&Bs[k][tx * TN + 4]);
            br[0]=b0.x; br[1]=b0.y; br[2]=b0.z; br[3]=b0.w;
            br[4]=b1.x; br[5]=b1.y; br[6]=b1.z; br[7]=b1.w;
            #pragma unroll
            for (int i = 0; i < TM; i++)
                #pragma unroll
                for (int j = 0; j < TN; j++)
                    acc[i][j] = fmaf(ar[i], br[j], acc[i][j]);
        }
        __syncthreads();
    }

    // write C
    int rowBase = blockIdx.y * BM + ty * TM;
    int colBase = blockIdx.x * BN + tx * TN;
    #pragma unroll
    for (int i = 0; i < TM; i++) {
        float4 o0 = make_float4(acc[i][0], acc[i][1], acc[i][2], acc[i][3]);
        float4 o1 = make_float4(acc[i][4], acc[i][5], acc[i][6], acc[i][7]);
        *(float4*)(C + (size_t)(rowBase + i) * G3 + colBase)     = o0;
        *(float4*)(C + (size_t)(rowBase + i) * G3 + colBase + 4) = o1;
    }
}

// ---------------- fused GRU update ----------------
// gi = v @ M + bvec (+ C2 row for enc2);  gh = G row + bhh
// r = sig(gi_r+gh_r); z = sig(gi_z+gh_z); n = tanh(gi_n + r*gh_n)
// h = (1-z)*n + z*h
__global__ void gru_update(const float* __restrict__ Mm, const float* __restrict__ bvec,
                           const float* __restrict__ bhh, const float* __restrict__ C2,
                           const float* __restrict__ G, const float* __restrict__ v,
                           float* __restrict__ h) {
    int j = blockIdx.x * blockDim.x + threadIdx.x;   // 0..767 (grid.x=3, block=256)
    int row = blockIdx.y;

    __shared__ float vs[DD];
    if (threadIdx.x < DD) vs[threadIdx.x] = v[row * DD + threadIdx.x];
    __syncthreads();

    float gi_r = bvec[j];
    float gi_z = bvec[j + HH];
    float gi_n = bvec[j + 2 * HH];
    #pragma unroll
    for (int d = 0; d < DD; d++) {
        float vd = vs[d];
        gi_r = fmaf(vd, Mm[d * G3 + j],          gi_r);
        gi_z = fmaf(vd, Mm[d * G3 + j + HH],     gi_z);
        gi_n = fmaf(vd, Mm[d * G3 + j + 2 * HH], gi_n);
    }
    if (C2 != nullptr) {
        const float* c = C2 + (size_t)row * G3;
        gi_r += c[j];
        gi_z += c[j + HH];
        gi_n += c[j + 2 * HH];
    }
    const float* grow = G + (size_t)row * G3;
    float gh_r = grow[j]          + bhh[j];
    float gh_z = grow[j + HH]     + bhh[j + HH];
    float gh_n = grow[j + 2 * HH] + bhh[j + 2 * HH];

    float r = 1.0f / (1.0f + expf(-(gi_r + gh_r)));
    float z = 1.0f / (1.0f + expf(-(gi_z + gh_z)));
    float n = tanhf(gi_n + r * gh_n);
    float ho = h[(size_t)row * HH + j];
    h[(size_t)row * HH + j] = (1.0f - z) * n + z * ho;
}

// ---------------- decoder head: h2n + mix + relu + pos ----------------
__global__ void h2n_pos(const float* __restrict__ h,
                        const float* __restrict__ h2nW, const float* __restrict__ h2nB,
                        const float* __restrict__ mixW, const float* __restrict__ mixB,
                        const float* __restrict__ base,
                        float* __restrict__ out_rel, float* __restrict__ out_pos) {
    int row = blockIdx.x;
    int tid = threadIdx.x;
    int warp = tid >> 5, lane = tid & 31;
    __shared__ float sn[5];

    if (warp < 5) {
        const float* hr = h + (size_t)row * HH;
        const float* wr = h2nW + warp * HH;
        float s = 0.0f;
        for (int i = lane; i < HH; i += 32) s = fmaf(hr[i], wr[i], s);
        #pragma unroll
        for (int o = 16; o > 0; o >>= 1) s += __shfl_down_sync(0xffffffffu, s, o);
        if (lane == 0) {
            float raw = s + h2nB[warp];
            float val;
            if (warp < 2) {
                val = raw;
            } else if (warp < 4) {
                float sp = raw > 0.0f ? raw + log1pf(expf(-raw)) : log1pf(expf(raw));
                val = 0.01f + 0.2f * sp;
            } else {
                val = 0.7f * tanhf(raw);
            }
            sn[warp] = val;
            out_rel[(size_t)row * 5 + warp] = val;
        }
    }
    __syncthreads();
    if (tid < DD) {
        float acc = mixB[tid];
        #pragma unroll
        for (int c = 0; c < 5; c++) acc = fmaf(sn[c], mixW[tid * 5 + c], acc);
        acc = acc > 0.0f ? acc : 0.0f;
        out_pos[(size_t)row * DD + tid] = base[(size_t)row * DD + tid] + acc;
    }
}

// ---------------- host orchestration ----------------
extern "C" void kernel_launch(void* const* d_in, const int* in_sizes, int n_in,
                              void* d_out, int out_size) {
    const float* observed = (const float*)d_in[0];
    const float* emb_W    = (const float*)d_in[1];
    const float* emb_b    = (const float*)d_in[2];
    const float* e1_Wih   = (const float*)d_in[3];
    const float* e1_Whh   = (const float*)d_in[4];
    const float* e1_bih   = (const float*)d_in[5];
    const float* e1_bhh   = (const float*)d_in[6];
    const float* e2_Wih   = (const float*)d_in[7];
    const float* e2_Whh   = (const float*)d_in[8];
    const float* e2_bih   = (const float*)d_in[9];
    const float* e2_bhh   = (const float*)d_in[10];
    const float* dec_Wih  = (const float*)d_in[11];
    const float* dec_Whh  = (const float*)d_in[12];
    const float* dec_bih  = (const float*)d_in[13];
    const float* dec_bhh  = (const float*)d_in[14];
    const float* h2n_W    = (const float*)d_in[15];
    const float* h2n_b    = (const float*)d_in[16];
    const float* mix_W    = (const float*)d_in[17];
    const float* mix_b    = (const float*)d_in[18];
    float* out = (float*)d_out;

    float *M1, *M2, *Md, *b1, *b2, *bd;
    float *W1T, *W2T, *WdT, *W2hT, *C2, *G, *h, *hinv, *v;
    cudaGetSymbolAddress((void**)&M1,  g_M1);
    cudaGetSymbolAddress((void**)&M2,  g_M2);
    cudaGetSymbolAddress((void**)&Md,  g_Md);
    cudaGetSymbolAddress((void**)&b1,  g_b1);
    cudaGetSymbolAddress((void**)&b2,  g_b2);
    cudaGetSymbolAddress((void**)&bd,  g_bd);
    cudaGetSymbolAddress((void**)&W1T, g_W1T);
    cudaGetSymbolAddress((void**)&W2T, g_W2T);
    cudaGetSymbolAddress((void**)&WdT, g_WdT);
    cudaGetSymbolAddress((void**)&W2hT,g_W2hT);
    cudaGetSymbolAddress((void**)&C2,  g_C2);
    cudaGetSymbolAddress((void**)&G,   g_G);
    cudaGetSymbolAddress((void**)&h,   g_h);
    cudaGetSymbolAddress((void**)&hinv,g_hinv);
    cudaGetSymbolAddress((void**)&v,   g_v);

    const int ND = NB * DD;           // 32768
    const int NH = NB * HH;           // 1572864
    float* rel_out  = out;                         // (12, 2048, 5)
    float* pred_out = out + (size_t)NPRED * NB * 5; // (12, 2048, 16)

    dim3 gemmGrid(G3 / BN, NB / BM);   // (18, 16)
    dim3 gruGrid(HH / 256, NB);        // (3, 2048)

    // ---- one-time prep (per call; deterministic) ----
    prep_combined<<<(G3 + 255) / 256, 256>>>(e1_Wih,  EE,        e1_bih,  emb_W, emb_b, M1, b1);
    prep_combined<<<(G3 + 255) / 256, 256>>>(e2_Wih,  EE + HH,   e2_bih,  emb_W, emb_b, M2, b2);
    prep_combined<<<(G3 + 255) / 256, 256>>>(dec_Wih, EE,        dec_bih, emb_W, emb_b, Md, bd);

    dim3 trGrid(G3 / 32, HH / 32), trBlock(32, 8);
    transpose_sub<<<trGrid, trBlock>>>(e1_Whh,  HH,      0,  W1T);
    transpose_sub<<<trGrid, trBlock>>>(e2_Whh,  HH,      0,  W2T);
    transpose_sub<<<trGrid, trBlock>>>(dec_Whh, HH,      0,  WdT);
    transpose_sub<<<trGrid, trBlock>>>(e2_Wih,  EE + HH, EE, W2hT);

    zero_kernel<<<(NH + 255) / 256, 256>>>(h, NH);

    // ---- encoder 1: backward velocities vel_b[t] = obs[7-t] - obs[6-t] ----
    for (int t = 0; t < TT - 1; t++) {
        sub_kernel<<<(ND + 255) / 256, 256>>>(observed + (size_t)(7 - t) * ND,
                                              observed + (size_t)(6 - t) * ND, v, ND);
        sgemm_kernel<<<gemmGrid, 256>>>(h, W1T, G);
        gru_update<<<gruGrid, 256>>>(M1, b1, e1_bhh, nullptr, G, v, h);
    }
    copy_kernel<<<(NH + 255) / 256, 256>>>(hinv, h, NH);

    // constant enc2 input contribution: C2 = h_inv @ e2_Wih[:,256:]^T
    sgemm_kernel<<<gemmGrid, 256>>>(hinv, W2hT, C2);

    zero_kernel<<<(NH + 255) / 256, 256>>>(h, NH);

    // ---- encoder 2: forward velocities vel_f[t] = obs[t+1] - obs[t] ----
    for (int t = 0; t < TT - 1; t++) {
        sub_kernel<<<(ND + 255) / 256, 256>>>(observed + (size_t)(t + 1) * ND,
                                              observed + (size_t)t * ND, v, ND);
        sgemm_kernel<<<gemmGrid, 256>>>(h, W2T, G);
        gru_update<<<gruGrid, 256>>>(M2, b2, e2_bhh, C2, G, v, h);
    }

    // ---- decoder: 12 autoregressive steps ----
    for (int k = 0; k < NPRED; k++) {
        const float *pa, *pb, *pbase;
        if (k == 0) {
            pa = observed + (size_t)7 * ND;
            pb = observed + (size_t)6 * ND;
            pbase = pa;
        } else if (k == 1) {
            pa = pred_out;                       // p0
            pb = observed + (size_t)7 * ND;
            pbase = pa;
        } else {
            pa = pred_out + (size_t)(k - 1) * ND; // p_{k-1}
            pb = pred_out + (size_t)(k - 2) * ND; // p_{k-2}
            pbase = pa;
        }
        sub_kernel<<<(ND + 255) / 256, 256>>>(pa, pb, v, ND);
        sgemm_kernel<<<gemmGrid, 256>>>(h, WdT, G);
        gru_update<<<gruGrid, 256>>>(Md, bd, dec_bhh, nullptr, G, v, h);
        h2n_pos<<<NB, 160>>>(h, h2n_W, h2n_b, mix_W, mix_b, pbase,
                             rel_out + (size_t)k * NB * 5,
                             pred_out + (size_t)k * ND);
    }
}

// round 3
// speedup vs baseline: 2.7330x; 2.7330x over previous
#include <cuda_runtime.h>
#include <cuda_bf16.h>
#include <cstdint>
#include <math.h>

// Problem constants (dataset-fixed: T=8, N=2048, E=256, H=768, D=16, n_predict=12)
#define NB    2048
#define DD    16
#define EE    256
#define HH    768
#define G3    2304        // 3*H
#define TT    8
#define NPRED 12
#define SCALEF 4.0f

// tcgen05 is only legal in the arch-SPECIFIC (sm_103a / sm_100a) device pass.
// The harness also runs a plain sm_103 pass (same __CUDA_ARCH__!), so gate on
// the accelerated-feature macros only.
#if defined(__CUDA_ARCH_FEAT_SM103_ALL) || defined(__CUDA_ARCH_FEAT_SM100_ALL) || \
    (defined(__CUDA_ARCH_SPECIFIC__) && (__CUDA_ARCH_SPECIFIC__ >= 1000))
#define HAS_TCG 1
#else
#define HAS_TCG 0
#endif

// ---------------- device scratch (no allocations allowed) ----------------
__device__ __align__(256) float g_M1[DD*G3];
__device__ __align__(256) float g_M2[DD*G3];
__device__ __align__(256) float g_Md[DD*G3];
__device__ __align__(256) float g_b1[G3];
__device__ __align__(256) float g_b2[G3];
__device__ __align__(256) float g_bd[G3];
__device__ __align__(256) __nv_bfloat16 g_Bh1[G3*HH];   // e1_Whh hi/lo
__device__ __align__(256) __nv_bfloat16 g_Bl1[G3*HH];
__device__ __align__(256) __nv_bfloat16 g_Bh2[G3*HH];   // e2_Whh
__device__ __align__(256) __nv_bfloat16 g_Bl2[G3*HH];
__device__ __align__(256) __nv_bfloat16 g_Bhd[G3*HH];   // dec_Whh
__device__ __align__(256) __nv_bfloat16 g_Bld[G3*HH];
__device__ __align__(256) __nv_bfloat16 g_Bh2x[G3*HH];  // e2_Wih[:,256:]
__device__ __align__(256) __nv_bfloat16 g_Bl2x[G3*HH];
__device__ __align__(256) float g_C2[NB*G3];    // h_inv @ e2_Wih[:,256:]^T
__device__ __align__(256) float g_G[NB*G3];     // gh buffer
__device__ __align__(256) float g_h[NB*HH];
__device__ __align__(256) float g_v[NB*DD];

// ---------------- small PTX helpers ----------------
__device__ __forceinline__ uint32_t smem_u32(const void* p) {
    uint32_t a;
    asm("{ .reg .u64 t; cvta.to.shared.u64 t, %1; cvt.u32.u64 %0, t; }"
        : "=r"(a) : "l"(p));
    return a;
}

__device__ __forceinline__ uint32_t elect_one() {
    uint32_t pred;
    asm volatile(
        "{\n\t.reg .pred p;\n\t"
        "elect.sync _|p, 0xFFFFFFFF;\n\t"
        "selp.b32 %0, 1, 0, p;\n\t}"
        : "=r"(pred));
    return pred;
}

__device__ __forceinline__ void mbar_init(uint32_t mbar, uint32_t cnt) {
    asm volatile("mbarrier.init.shared.b64 [%0], %1;" :: "r"(mbar), "r"(cnt) : "memory");
}
__device__ __forceinline__ void mbar_inval(uint32_t mbar) {
    asm volatile("mbarrier.inval.shared.b64 [%0];" :: "r"(mbar) : "memory");
}
__device__ __forceinline__ void mbar_wait(uint32_t mbar, uint32_t parity) {
    uint32_t done;
    asm volatile(
        "{\n\t.reg .pred p;\n\t"
        "mbarrier.try_wait.parity.acquire.cta.shared::cta.b64 p, [%1], %2;\n\t"
        "selp.b32 %0, 1, 0, p;\n\t}"
        : "=r"(done) : "r"(mbar), "r"(parity) : "memory");
    while (!done) {
        asm volatile(
            "{\n\t.reg .pred p;\n\t"
            "mbarrier.try_wait.parity.acquire.cta.shared::cta.b64 p, [%1], %2, 0x989680;\n\t"
            "selp.b32 %0, 1, 0, p;\n\t}"
            : "=r"(done) : "r"(mbar), "r"(parity) : "memory");
    }
}

#define FENCE_ASYNC_SHARED() asm volatile("fence.proxy.async.shared::cta;" ::: "memory")

__device__ __forceinline__ uint32_t swz128(uint32_t off) {
    return off ^ ((off >> 3) & 0x70);
}

__device__ __forceinline__ void split2(float a, float b, uint32_t& hi, uint32_t& lo) {
    __nv_bfloat16 ha = __float2bfloat16(a);
    __nv_bfloat16 hb = __float2bfloat16(b);
    __nv_bfloat162 hh; hh.x = ha; hh.y = hb;
    hi = *reinterpret_cast<uint32_t*>(&hh);
    __nv_bfloat162 ll;
    ll.x = __float2bfloat16(a - __bfloat162float(ha));
    ll.y = __float2bfloat16(b - __bfloat162float(hb));
    lo = *reinterpret_cast<uint32_t*>(&ll);
}

#if HAS_TCG
// ------- tcgen05-only macros (compiled exclusively in the sm_103a pass) -------
#define TC_ALLOC(smem_addr, n) \
    asm volatile("tcgen05.alloc.cta_group::1.sync.aligned.shared::cta.b32 [%0], %1;" \
                 :: "r"(smem_addr), "r"((uint32_t)(n)) : "memory")
#define TC_DEALLOC(tmem_addr, n) \
    asm volatile("tcgen05.dealloc.cta_group::1.sync.aligned.b32 %0, %1;" \
                 :: "r"(tmem_addr), "r"((uint32_t)(n)))
#define TC_RELINQUISH() \
    asm volatile("tcgen05.relinquish_alloc_permit.cta_group::1.sync.aligned;")
#define TC_COMMIT(mbar) \
    asm volatile("tcgen05.commit.cta_group::1.mbarrier::arrive::one.shared::cluster.b64 [%0];" \
                 :: "r"(mbar) : "memory")
#define TC_FENCE_AFTER()  asm volatile("tcgen05.fence::after_thread_sync;" ::: "memory")
#define TC_FENCE_BEFORE() asm volatile("tcgen05.fence::before_thread_sync;" ::: "memory")
#define TC_WAIT_LD()      asm volatile("tcgen05.wait::ld.sync.aligned;" ::: "memory")

#define TC_LD_X32(r, addr) \
    asm volatile( \
        "tcgen05.ld.sync.aligned.32x32b.x32.b32 " \
        "{%0, %1, %2, %3, %4, %5, %6, %7, " \
        " %8, %9, %10, %11, %12, %13, %14, %15, " \
        " %16, %17, %18, %19, %20, %21, %22, %23, " \
        " %24, %25, %26, %27, %28, %29, %30, %31}, [%32];" \
        : "=r"((r)[0]),  "=r"((r)[1]),  "=r"((r)[2]),  "=r"((r)[3]), \
          "=r"((r)[4]),  "=r"((r)[5]),  "=r"((r)[6]),  "=r"((r)[7]), \
          "=r"((r)[8]),  "=r"((r)[9]),  "=r"((r)[10]), "=r"((r)[11]), \
          "=r"((r)[12]), "=r"((r)[13]), "=r"((r)[14]), "=r"((r)[15]), \
          "=r"((r)[16]), "=r"((r)[17]), "=r"((r)[18]), "=r"((r)[19]), \
          "=r"((r)[20]), "=r"((r)[21]), "=r"((r)[22]), "=r"((r)[23]), \
          "=r"((r)[24]), "=r"((r)[25]), "=r"((r)[26]), "=r"((r)[27]), \
          "=r"((r)[28]), "=r"((r)[29]), "=r"((r)[30]), "=r"((r)[31]) \
        : "r"(addr))

// SS-form bf16 MMA, cg1, fp32 accumulate in TMEM
__device__ __forceinline__ void mma_bf16_ss(uint32_t d, uint64_t ad, uint64_t bd,
                                            uint32_t idesc, uint32_t en) {
    asm volatile(
        "{\n\t.reg .pred p;\n\t"
        "setp.ne.u32 p, %5, 0;\n\t"
        "tcgen05.mma.cta_group::1.kind::f16 [%0], %1, %2, %3, {%4, %4, %4, %4}, p;\n\t}"
        :: "r"(d), "l"(ad), "l"(bd), "r"(idesc), "r"(0u), "r"(en) : "memory");
}

// idesc: dtype=F32, atype=btype=BF16, N=128, M=128, K-major both
#define MMA_IDESC ((1u<<4) | (1u<<7) | (1u<<10) | ((128u/8u)<<17) | ((128u/16u)<<24))

// SW128 K-major smem descriptor (LBO=1 (16B), SBO=64 (1024B), layout=SW128, Blackwell v1)
__device__ __forceinline__ uint64_t make_desc_sw128(uint32_t addr) {
    const uint64_t base =
        (uint64_t(2)  << 61) | (uint64_t(1) << 46) | (uint64_t(64) << 32) | (uint64_t(1) << 16);
    return base | ((uint64_t)(addr >> 4) & 0x3FFF);
}
#endif  // HAS_TCG

// ---------------- GEMM: C(2048x2304) = A(2048x768) @ B(2304x768)^T ----------
// tcgen05 path: 3xbf16 emulation, C = Ahi*Bhi + Ahi*Blo + Alo*Bhi (fp32 TMEM acc)
// fallback path (plain sm_103 pass): fp32 FFMA SGEMM on reconstructed hi+lo.
#define KC      64                    // K elems per chunk (64 bf16 = 128B rows)
#define NCHUNK  (HH / KC)             // 12
#define TILEB   16384                 // 128 rows x 128B
#define STAGEB  (4 * TILEB)           // Ahi, Alo, Bhi, Blo
#define GEMM_SMEM (1024 + 2 * STAGEB) // 132096 bytes

__global__ void __launch_bounds__(256, 1)
gemm_tc(const float* __restrict__ A,
        const __nv_bfloat16* __restrict__ Bhg,
        const __nv_bfloat16* __restrict__ Blg,
        float* __restrict__ C) {
#if HAS_TCG
    extern __shared__ char smem[];
    uint32_t sb = smem_u32(smem);
    int tid = threadIdx.x;
    int wid = tid >> 5, lane = tid & 31;

    // smem map: [0] tmem ptr, [16]/[24] mbarriers, tiles from 1024
    if (wid == 0) TC_ALLOC(sb, 512);
    if (tid == 0) { mbar_init(sb + 16, 1); mbar_init(sb + 24, 1); }
    __syncthreads();
    uint32_t tmem;
    asm volatile("ld.shared.b32 %0, [%1];" : "=r"(tmem) : "r"(sb));

    const float* Ab = A + (size_t)blockIdx.y * 128 * HH;
    const __nv_bfloat16* Bhb = Bhg + (size_t)blockIdx.x * 128 * HH;
    const __nv_bfloat16* Blb = Blg + (size_t)blockIdx.x * 128 * HH;

    for (int i = 0; i < NCHUNK; i++) {
        int b = i & 1;
        char* sAh = smem + 1024 + b * STAGEB;
        char* sAl = sAh + TILEB;
        char* sBh = sAl + TILEB;
        char* sBl = sBh + TILEB;
        uint32_t bufu = sb + 1024 + b * STAGEB;

        if (i >= 2) mbar_wait(sb + 16 + 8 * b, ((i - 2) >> 1) & 1);

        int kc0 = i * KC;
        // A: 128 rows x 64 fp32 -> bf16 hi/lo (8 floats per slot, 1024 slots)
        #pragma unroll
        for (int j = 0; j < 4; j++) {
            int u = tid + j * 256;
            int row = u >> 3, q = u & 7;
            const float4* g = (const float4*)(Ab + (size_t)row * HH + kc0 + q * 8);
            float4 x0 = g[0], x1 = g[1];
            uint4 vh, vl;
            split2(x0.x, x0.y, vh.x, vl.x);
            split2(x0.z, x0.w, vh.y, vl.y);
            split2(x1.x, x1.y, vh.z, vl.z);
            split2(x1.z, x1.w, vh.w, vl.w);
            uint32_t off = swz128(row * 128 + q * 16);
            *(uint4*)(sAh + off) = vh;
            *(uint4*)(sAl + off) = vl;
        }
        // B: 128 rows x 64 bf16 (hi and lo), 16B units
        #pragma unroll
        for (int j = 0; j < 4; j++) {
            int u = tid + j * 256;
            int row = u >> 3, q = u & 7;
            size_t go = (size_t)row * HH + kc0 + q * 8;
            uint4 vh = *(const uint4*)(Bhb + go);
            uint4 vl = *(const uint4*)(Blb + go);
            uint32_t off = swz128(row * 128 + q * 16);
            *(uint4*)(sBh + off) = vh;
            *(uint4*)(sBl + off) = vl;
        }
        FENCE_ASYNC_SHARED();
        __syncthreads();

        if (wid == 0 && elect_one()) {
            uint64_t dAh = make_desc_sw128(bufu);
            uint64_t dAl = make_desc_sw128(bufu + TILEB);
            uint64_t dBh = make_desc_sw128(bufu + 2 * TILEB);
            uint64_t dBl = make_desc_sw128(bufu + 3 * TILEB);
            #pragma unroll
            for (int s = 0; s < 4; s++) {   // K=16 bf16 per MMA, +32B per step
                uint64_t o = (uint64_t)(s * 2);
                mma_bf16_ss(tmem, dAh + o, dBh + o, MMA_IDESC, !(i == 0 && s == 0));
                mma_bf16_ss(tmem, dAh + o, dBl + o, MMA_IDESC, 1u);
                mma_bf16_ss(tmem, dAl + o, dBh + o, MMA_IDESC, 1u);
            }
            TC_COMMIT(sb + 16 + 8 * b);
        }
    }

    // drain: waits in the loop consumed phases up to commit idx 4 on each mbar;
    // the final (6th) commit on each flips to parity-1-completed.
    mbar_wait(sb + 16, 1);
    mbar_wait(sb + 24, 1);
    TC_FENCE_AFTER();

    // epilogue: 8 warps; warp w: rows (w&3)*32+lane, cols (w>>2)*64..+64
    int sub = wid & 3, half = wid >> 2;
    uint32_t r0[32], r1[32];
    TC_LD_X32(r0, tmem + half * 64);
    TC_LD_X32(r1, tmem + half * 64 + 32);
    TC_WAIT_LD();
    TC_FENCE_BEFORE();

    int rowg = blockIdx.y * 128 + sub * 32 + lane;
    float* crow = C + (size_t)rowg * G3 + blockIdx.x * 128 + half * 64;
    #pragma unroll
    for (int c = 0; c < 32; c += 4) {
        *(float4*)(crow + c) = make_float4(
            __uint_as_float(r0[c]), __uint_as_float(r0[c+1]),
            __uint_as_float(r0[c+2]), __uint_as_float(r0[c+3]));
        *(float4*)(crow + 32 + c) = make_float4(
            __uint_as_float(r1[c]), __uint_as_float(r1[c+1]),
            __uint_as_float(r1[c+2]), __uint_as_float(r1[c+3]));
    }

    __syncthreads();
    if (tid == 0) { mbar_inval(sb + 16); mbar_inval(sb + 24); }
    __syncthreads();
    if (wid == 0) {
        TC_RELINQUISH();
        TC_DEALLOC(tmem, 512);
    }
#else
    // ---------------- FFMA fallback (plain sm_103 pass only) ----------------
    extern __shared__ char smem[];
    float* As = (float*)smem;              // [16][128]  As[k][m]
    float* Bs = As + 16 * 128;             // [16][128]  Bs[k][n]

    int tid = threadIdx.x;
    int ty = tid >> 4;        // 0..15
    int tx = tid & 15;        // 0..15

    const float* Ab = A + (size_t)blockIdx.y * 128 * HH;
    const __nv_bfloat16* Bhb = Bhg + (size_t)blockIdx.x * 128 * HH;
    const __nv_bfloat16* Blb = Blg + (size_t)blockIdx.x * 128 * HH;

    float acc[8][8];
    #pragma unroll
    for (int i = 0; i < 8; i++)
        #pragma unroll
        for (int j = 0; j < 8; j++) acc[i][j] = 0.0f;

    for (int kt = 0; kt < HH; kt += 16) {
        #pragma unroll
        for (int i = 0; i < 2; i++) {
            int idx = tid + i * 256;
            int r  = idx >> 2;
            int k4 = (idx & 3) << 2;
            float4 av = *(const float4*)(Ab + (size_t)r * HH + kt + k4);
            As[(k4 + 0) * 128 + r] = av.x;
            As[(k4 + 1) * 128 + r] = av.y;
            As[(k4 + 2) * 128 + r] = av.z;
            As[(k4 + 3) * 128 + r] = av.w;
        }
        {
            int n  = tid >> 1;
            int kq = (tid & 1) * 8;
            size_t go = (size_t)n * HH + kt + kq;
            uint4 vh = *(const uint4*)(Bhb + go);
            uint4 vl = *(const uint4*)(Blb + go);
            const __nv_bfloat16* ph = (const __nv_bfloat16*)&vh;
            const __nv_bfloat16* pl = (const __nv_bfloat16*)&vl;
            #pragma unroll
            for (int e = 0; e < 8; e++)
                Bs[(kq + e) * 128 + n] = __bfloat162float(ph[e]) + __bfloat162float(pl[e]);
        }
        __syncthreads();

        #pragma unroll
        for (int k = 0; k < 16; k++) {
            float ar[8], br[8];
            float4 a0 = *(const float4*)(&As[k * 128 + ty * 8]);
            float4 a1 = *(const float4*)(&As[k * 128 + ty * 8 + 4]);
            ar[0]=a0.x; ar[1]=a0.y; ar[2]=a0.z; ar[3]=a0.w;
            ar[4]=a1.x; ar[5]=a1.y; ar[6]=a1.z; ar[7]=a1.w;
            float4 b0 = *(const float4*)(&Bs[k * 128 + tx * 8]);
            float4 b1 = *(const float4*)(&Bs[k * 128 + tx * 8 + 4]);
            br[0]=b0.x; br[1]=b0.y; br[2]=b0.z; br[3]=b0.w;
            br[4]=b1.x; br[5]=b1.y; br[6]=b1.z; br[7]=b1.w;
            #pragma unroll
            for (int i = 0; i < 8; i++)
                #pragma unroll
                for (int j = 0; j < 8; j++)
                    acc[i][j] = fmaf(ar[i], br[j], acc[i][j]);
        }
        __syncthreads();
    }

    int rowBase = blockIdx.y * 128 + ty * 8;
    int colBase = blockIdx.x * 128 + tx * 8;
    #pragma unroll
    for (int i = 0; i < 8; i++) {
        *(float4*)(C + (size_t)(rowBase + i) * G3 + colBase) =
            make_float4(acc[i][0], acc[i][1], acc[i][2], acc[i][3]);
        *(float4*)(C + (size_t)(rowBase + i) * G3 + colBase + 4) =
            make_float4(acc[i][4], acc[i][5], acc[i][6], acc[i][7]);
    }
#endif
}

// ---------------- tiny utility kernels ----------------
__global__ void zero_kernel(float* p, int n) {
    int i = blockIdx.x * blockDim.x + threadIdx.x;
    if (i < n) p[i] = 0.0f;
}

__global__ void sub_kernel(const float* __restrict__ a, const float* __restrict__ b,
                           float* __restrict__ v, int n) {
    int i = blockIdx.x * blockDim.x + threadIdx.x;
    if (i < n) v[i] = a[i] - b[i];
}

// bf16 hi/lo split of a (G3 x HH) slice of a weight matrix
__global__ void conv_bf16(const float* __restrict__ W, int ld, int off,
                          __nv_bfloat16* __restrict__ hi, __nv_bfloat16* __restrict__ lo) {
    int idx = blockIdx.x * blockDim.x + threadIdx.x;
    if (idx >= G3 * HH) return;
    int j = idx / HH, k = idx % HH;
    float x = W[(size_t)j * ld + off + k];
    __nv_bfloat16 h = __float2bfloat16(x);
    hi[idx] = h;
    lo[idx] = __float2bfloat16(x - __bfloat162float(h));
}

// Fold embed() into Wih:  M[d][j] = SCALE * sum_e embW[e][d] * Wih[j][e]
//                         b[j]    = bih[j] + sum_e embB[e]  * Wih[j][e]
__global__ void prep_combined(const float* __restrict__ Wih, int ldw,
                              const float* __restrict__ bih,
                              const float* __restrict__ embW,
                              const float* __restrict__ embB,
                              float* __restrict__ Mout, float* __restrict__ bout) {
    int j = blockIdx.x * blockDim.x + threadIdx.x;
    if (j >= G3) return;
    float accM[DD];
    #pragma unroll
    for (int d = 0; d < DD; d++) accM[d] = 0.0f;
    float accb = 0.0f;
    const float* wrow = Wih + (size_t)j * ldw;
    for (int e = 0; e < EE; e++) {
        float w = wrow[e];
        accb += embB[e] * w;
        const float* er = embW + e * DD;
        #pragma unroll
        for (int d = 0; d < DD; d++) accM[d] += er[d] * w;
    }
    #pragma unroll
    for (int d = 0; d < DD; d++) Mout[d * G3 + j] = SCALEF * accM[d];
    bout[j] = accb + bih[j];
}

// ---------------- fused GRU update ----------------
__global__ void gru_update(const float* __restrict__ Mm, const float* __restrict__ bvec,
                           const float* __restrict__ bhh, const float* __restrict__ C2,
                           const float* __restrict__ G, const float* __restrict__ v,
                           float* __restrict__ h) {
    int j = blockIdx.x * blockDim.x + threadIdx.x;   // 0..767
    int row = blockIdx.y;

    __shared__ float vs[DD];
    if (threadIdx.x < DD) vs[threadIdx.x] = v[row * DD + threadIdx.x];
    __syncthreads();

    float gi_r = bvec[j];
    float gi_z = bvec[j + HH];
    float gi_n = bvec[j + 2 * HH];
    #pragma unroll
    for (int d = 0; d < DD; d++) {
        float vd = vs[d];
        gi_r = fmaf(vd, Mm[d * G3 + j],          gi_r);
        gi_z = fmaf(vd, Mm[d * G3 + j + HH],     gi_z);
        gi_n = fmaf(vd, Mm[d * G3 + j + 2 * HH], gi_n);
    }
    if (C2 != nullptr) {
        const float* c = C2 + (size_t)row * G3;
        gi_r += c[j];
        gi_z += c[j + HH];
        gi_n += c[j + 2 * HH];
    }
    float gh_r, gh_z, gh_n;
    if (G != nullptr) {
        const float* grow = G + (size_t)row * G3;
        gh_r = grow[j]          + bhh[j];
        gh_z = grow[j + HH]     + bhh[j + HH];
        gh_n = grow[j + 2 * HH] + bhh[j + 2 * HH];
    } else {
        gh_r = bhh[j];
        gh_z = bhh[j + HH];
        gh_n = bhh[j + 2 * HH];
    }

    float r = 1.0f / (1.0f + expf(-(gi_r + gh_r)));
    float z = 1.0f / (1.0f + expf(-(gi_z + gh_z)));
    float n = tanhf(gi_n + r * gh_n);
    float ho = h[(size_t)row * HH + j];
    h[(size_t)row * HH + j] = (1.0f - z) * n + z * ho;
}

// ---------------- decoder head: h2n + mix + relu + pos ----------------
__global__ void h2n_pos(const float* __restrict__ h,
                        const float* __restrict__ h2nW, const float* __restrict__ h2nB,
                        const float* __restrict__ mixW, const float* __restrict__ mixB,
                        const float* __restrict__ base,
                        float* __restrict__ out_rel, float* __restrict__ out_pos) {
    int row = blockIdx.x;
    int tid = threadIdx.x;
    int warp = tid >> 5, lane = tid & 31;
    __shared__ float sn[5];

    if (warp < 5) {
        const float* hr = h + (size_t)row * HH;
        const float* wr = h2nW + warp * HH;
        float s = 0.0f;
        for (int i = lane; i < HH; i += 32) s = fmaf(hr[i], wr[i], s);
        #pragma unroll
        for (int o = 16; o > 0; o >>= 1) s += __shfl_down_sync(0xffffffffu, s, o);
        if (lane == 0) {
            float raw = s + h2nB[warp];
            float val;
            if (warp < 2) {
                val = raw;
            } else if (warp < 4) {
                float sp = raw > 0.0f ? raw + log1pf(expf(-raw)) : log1pf(expf(raw));
                val = 0.01f + 0.2f * sp;
            } else {
                val = 0.7f * tanhf(raw);
            }
            sn[warp] = val;
            out_rel[(size_t)row * 5 + warp] = val;
        }
    }
    __syncthreads();
    if (tid < DD) {
        float acc = mixB[tid];
        #pragma unroll
        for (int c = 0; c < 5; c++) acc = fmaf(sn[c], mixW[tid * 5 + c], acc);
        acc = acc > 0.0f ? acc : 0.0f;
        out_pos[(size_t)row * DD + tid] = base[(size_t)row * DD + tid] + acc;
    }
}

// ---------------- host orchestration ----------------
extern "C" void kernel_launch(void* const* d_in, const int* in_sizes, int n_in,
                              void* d_out, int out_size) {
    const float* observed = (const float*)d_in[0];
    const float* emb_W    = (const float*)d_in[1];
    const float* emb_b    = (const float*)d_in[2];
    const float* e1_Wih   = (const float*)d_in[3];
    const float* e1_Whh   = (const float*)d_in[4];
    const float* e1_bih   = (const float*)d_in[5];
    const float* e1_bhh   = (const float*)d_in[6];
    const float* e2_Wih   = (const float*)d_in[7];
    const float* e2_Whh   = (const float*)d_in[8];
    const float* e2_bih   = (const float*)d_in[9];
    const float* e2_bhh   = (const float*)d_in[10];
    const float* dec_Wih  = (const float*)d_in[11];
    const float* dec_Whh  = (const float*)d_in[12];
    const float* dec_bih  = (const float*)d_in[13];
    const float* dec_bhh  = (const float*)d_in[14];
    const float* h2n_W    = (const float*)d_in[15];
    const float* h2n_b    = (const float*)d_in[16];
    const float* mix_W    = (const float*)d_in[17];
    const float* mix_b    = (const float*)d_in[18];
    float* out = (float*)d_out;

    float *M1, *M2, *Md, *b1, *b2, *bd, *C2, *G, *h, *v;
    __nv_bfloat16 *Bh1, *Bl1, *Bh2, *Bl2, *Bhd, *Bld, *Bh2x, *Bl2x;
    cudaGetSymbolAddress((void**)&M1,  g_M1);
    cudaGetSymbolAddress((void**)&M2,  g_M2);
    cudaGetSymbolAddress((void**)&Md,  g_Md);
    cudaGetSymbolAddress((void**)&b1,  g_b1);
    cudaGetSymbolAddress((void**)&b2,  g_b2);
    cudaGetSymbolAddress((void**)&bd,  g_bd);
    cudaGetSymbolAddress((void**)&Bh1, g_Bh1);
    cudaGetSymbolAddress((void**)&Bl1, g_Bl1);
    cudaGetSymbolAddress((void**)&Bh2, g_Bh2);
    cudaGetSymbolAddress((void**)&Bl2, g_Bl2);
    cudaGetSymbolAddress((void**)&Bhd, g_Bhd);
    cudaGetSymbolAddress((void**)&Bld, g_Bld);
    cudaGetSymbolAddress((void**)&Bh2x,g_Bh2x);
    cudaGetSymbolAddress((void**)&Bl2x,g_Bl2x);
    cudaGetSymbolAddress((void**)&C2,  g_C2);
    cudaGetSymbolAddress((void**)&G,   g_G);
    cudaGetSymbolAddress((void**)&h,   g_h);
    cudaGetSymbolAddress((void**)&v,   g_v);

    cudaFuncSetAttribute(gemm_tc, cudaFuncAttributeMaxDynamicSharedMemorySize, GEMM_SMEM);

    const int ND = NB * DD;           // 32768
    const int NH = NB * HH;           // 1572864
    float* rel_out  = out;                          // (12, 2048, 5)
    float* pred_out = out + (size_t)NPRED * NB * 5; // (12, 2048, 16)

    dim3 gemmGrid(G3 / 128, NB / 128);   // (18, 16)
    dim3 gruGrid(HH / 256, NB);          // (3, 2048)
    const int WELEM = G3 * HH;

    // ---- one-time prep (per call; deterministic) ----
    prep_combined<<<(G3 + 255) / 256, 256>>>(e1_Wih,  EE,      e1_bih,  emb_W, emb_b, M1, b1);
    prep_combined<<<(G3 + 255) / 256, 256>>>(e2_Wih,  EE + HH, e2_bih,  emb_W, emb_b, M2, b2);
    prep_combined<<<(G3 + 255) / 256, 256>>>(dec_Wih, EE,      dec_bih, emb_W, emb_b, Md, bd);

    conv_bf16<<<(WELEM + 255) / 256, 256>>>(e1_Whh,  HH,      0,  Bh1,  Bl1);
    conv_bf16<<<(WELEM + 255) / 256, 256>>>(e2_Whh,  HH,      0,  Bh2,  Bl2);
    conv_bf16<<<(WELEM + 255) / 256, 256>>>(dec_Whh, HH,      0,  Bhd,  Bld);
    conv_bf16<<<(WELEM + 255) / 256, 256>>>(e2_Wih,  EE + HH, EE, Bh2x, Bl2x);

    zero_kernel<<<(NH + 255) / 256, 256>>>(h, NH);

    // ---- encoder 1: backward velocities vel_b[t] = obs[7-t] - obs[6-t] ----
    for (int t = 0; t < TT - 1; t++) {
        sub_kernel<<<(ND + 255) / 256, 256>>>(observed + (size_t)(7 - t) * ND,
                                              observed + (size_t)(6 - t) * ND, v, ND);
        const float* Gp = nullptr;
        if (t > 0) {   // t==0: h==0 -> gh==0
            gemm_tc<<<gemmGrid, 256, GEMM_SMEM>>>(h, Bh1, Bl1, G);
            Gp = G;
        }
        gru_update<<<gruGrid, 256>>>(M1, b1, e1_bhh, nullptr, Gp, v, h);
    }

    // constant enc2 input contribution: C2 = h_inv @ e2_Wih[:,256:]^T (h currently == h_inv)
    gemm_tc<<<gemmGrid, 256, GEMM_SMEM>>>(h, Bh2x, Bl2x, C2);

    zero_kernel<<<(NH + 255) / 256, 256>>>(h, NH);

    // ---- encoder 2: forward velocities vel_f[t] = obs[t+1] - obs[t] ----
    for (int t = 0; t < TT - 1; t++) {
        sub_kernel<<<(ND + 255) / 256, 256>>>(observed + (size_t)(t + 1) * ND,
                                              observed + (size_t)t * ND, v, ND);
        const float* Gp = nullptr;
        if (t > 0) {
            gemm_tc<<<gemmGrid, 256, GEMM_SMEM>>>(h, Bh2, Bl2, G);
            Gp = G;
        }
        gru_update<<<gruGrid, 256>>>(M2, b2, e2_bhh, C2, Gp, v, h);
    }

    // ---- decoder: 12 autoregressive steps ----
    for (int k = 0; k < NPRED; k++) {
        const float *pa, *pb, *pbase;
        if (k == 0) {
            pa = observed + (size_t)7 * ND;
            pb = observed + (size_t)6 * ND;
            pbase = pa;
        } else if (k == 1) {
            pa = pred_out;                        // p0
            pb = observed + (size_t)7 * ND;
            pbase = pa;
        } else {
            pa = pred_out + (size_t)(k - 1) * ND; // p_{k-1}
            pb = pred_out + (size_t)(k - 2) * ND; // p_{k-2}
            pbase = pa;
        }
        sub_kernel<<<(ND + 255) / 256, 256>>>(pa, pb, v, ND);
        gemm_tc<<<gemmGrid, 256, GEMM_SMEM>>>(h, Bhd, Bld, G);
        gru_update<<<gruGrid, 256>>>(Md, bd, dec_bhh, nullptr, G, v, h);
        h2n_pos<<<NB, 160>>>(h, h2n_W, h2n_b, mix_W, mix_b, pbase,
                             rel_out + (size_t)k * NB * 5,
                             pred_out + (size_t)k * ND);
    }
}

// round 4
// speedup vs baseline: 3.2115x; 1.1751x over previous
#include <cuda_runtime.h>
#include <cuda_bf16.h>
#include <cstdint>
#include <math.h>

// Problem constants (dataset-fixed: T=8, N=2048, E=256, H=768, D=16, n_predict=12)
#define NB    2048
#define DD    16
#define EE    256
#define HH    768
#define G3    2304        // 3*H
#define TT    8
#define NPRED 12
#define SCALEF 4.0f

// tcgen05 is only legal in the arch-SPECIFIC (sm_103a / sm_100a) device pass.
// The harness also runs a plain sm_103 pass (same __CUDA_ARCH__!), so gate on
// the accelerated-feature macros only.
#if defined(__CUDA_ARCH_FEAT_SM103_ALL) || defined(__CUDA_ARCH_FEAT_SM100_ALL) || \
    (defined(__CUDA_ARCH_SPECIFIC__) && (__CUDA_ARCH_SPECIFIC__ >= 1000))
#define HAS_TCG 1
#else
#define HAS_TCG 0
#endif

// ---------------- device scratch (no allocations allowed) ----------------
__device__ __align__(256) float g_M1[DD*G3];
__device__ __align__(256) float g_M2[DD*G3];
__device__ __align__(256) float g_Md[DD*G3];
__device__ __align__(256) float g_b1[G3];
__device__ __align__(256) float g_b2[G3];
__device__ __align__(256) float g_bd[G3];
__device__ __align__(256) __nv_bfloat16 g_Bh1[G3*HH];   // e1_Whh hi/lo
__device__ __align__(256) __nv_bfloat16 g_Bl1[G3*HH];
__device__ __align__(256) __nv_bfloat16 g_Bh2[G3*HH];   // e2_Whh
__device__ __align__(256) __nv_bfloat16 g_Bl2[G3*HH];
__device__ __align__(256) __nv_bfloat16 g_Bhd[G3*HH];   // dec_Whh
__device__ __align__(256) __nv_bfloat16 g_Bld[G3*HH];
__device__ __align__(256) __nv_bfloat16 g_Bh2x[G3*HH];  // e2_Wih[:,256:]
__device__ __align__(256) __nv_bfloat16 g_Bl2x[G3*HH];
__device__ __align__(256) __nv_bfloat16 g_Ah[NB*HH];    // h split hi/lo (GEMM A operand)
__device__ __align__(256) __nv_bfloat16 g_Al[NB*HH];
__device__ __align__(256) float g_C2[NB*G3];    // h_inv @ e2_Wih[:,256:]^T
__device__ __align__(256) float g_G[NB*G3];     // gh buffer
__device__ __align__(256) float g_h[NB*HH];

// ---------------- small PTX helpers ----------------
__device__ __forceinline__ uint32_t smem_u32(const void* p) {
    uint32_t a;
    asm("{ .reg .u64 t; cvta.to.shared.u64 t, %1; cvt.u32.u64 %0, t; }"
        : "=r"(a) : "l"(p));
    return a;
}

__device__ __forceinline__ uint32_t elect_one() {
    uint32_t pred;
    asm volatile(
        "{\n\t.reg .pred p;\n\t"
        "elect.sync _|p, 0xFFFFFFFF;\n\t"
        "selp.b32 %0, 1, 0, p;\n\t}"
        : "=r"(pred));
    return pred;
}

__device__ __forceinline__ void mbar_init(uint32_t mbar, uint32_t cnt) {
    asm volatile("mbarrier.init.shared.b64 [%0], %1;" :: "r"(mbar), "r"(cnt) : "memory");
}
__device__ __forceinline__ void mbar_inval(uint32_t mbar) {
    asm volatile("mbarrier.inval.shared.b64 [%0];" :: "r"(mbar) : "memory");
}
__device__ __forceinline__ void mbar_wait(uint32_t mbar, uint32_t parity) {
    uint32_t done;
    asm volatile(
        "{\n\t.reg .pred p;\n\t"
        "mbarrier.try_wait.parity.acquire.cta.shared::cta.b64 p, [%1], %2;\n\t"
        "selp.b32 %0, 1, 0, p;\n\t}"
        : "=r"(done) : "r"(mbar), "r"(parity) : "memory");
    while (!done) {
        asm volatile(
            "{\n\t.reg .pred p;\n\t"
            "mbarrier.try_wait.parity.acquire.cta.shared::cta.b64 p, [%1], %2, 0x989680;\n\t"
            "selp.b32 %0, 1, 0, p;\n\t}"
            : "=r"(done) : "r"(mbar), "r"(parity) : "memory");
    }
}

#define FENCE_ASYNC_SHARED() asm volatile("fence.proxy.async.shared::cta;" ::: "memory")

__device__ __forceinline__ uint32_t swz128(uint32_t off) {
    return off ^ ((off >> 3) & 0x70);
}

#if HAS_TCG
// ------- tcgen05-only macros (compiled exclusively in the sm_103a pass) -------
#define TC_ALLOC(smem_addr, n) \
    asm volatile("tcgen05.alloc.cta_group::1.sync.aligned.shared::cta.b32 [%0], %1;" \
                 :: "r"(smem_addr), "r"((uint32_t)(n)) : "memory")
#define TC_DEALLOC(tmem_addr, n) \
    asm volatile("tcgen05.dealloc.cta_group::1.sync.aligned.b32 %0, %1;" \
                 :: "r"(tmem_addr), "r"((uint32_t)(n)))
#define TC_RELINQUISH() \
    asm volatile("tcgen05.relinquish_alloc_permit.cta_group::1.sync.aligned;")
#define TC_COMMIT(mbar) \
    asm volatile("tcgen05.commit.cta_group::1.mbarrier::arrive::one.shared::cluster.b64 [%0];" \
                 :: "r"(mbar) : "memory")
#define TC_FENCE_AFTER()  asm volatile("tcgen05.fence::after_thread_sync;" ::: "memory")
#define TC_FENCE_BEFORE() asm volatile("tcgen05.fence::before_thread_sync;" ::: "memory")
#define TC_WAIT_LD()      asm volatile("tcgen05.wait::ld.sync.aligned;" ::: "memory")

#define TC_LD_X32(r, addr) \
    asm volatile( \
        "tcgen05.ld.sync.aligned.32x32b.x32.b32 " \
        "{%0, %1, %2, %3, %4, %5, %6, %7, " \
        " %8, %9, %10, %11, %12, %13, %14, %15, " \
        " %16, %17, %18, %19, %20, %21, %22, %23, " \
        " %24, %25, %26, %27, %28, %29, %30, %31}, [%32];" \
        : "=r"((r)[0]),  "=r"((r)[1]),  "=r"((r)[2]),  "=r"((r)[3]), \
          "=r"((r)[4]),  "=r"((r)[5]),  "=r"((r)[6]),  "=r"((r)[7]), \
          "=r"((r)[8]),  "=r"((r)[9]),  "=r"((r)[10]), "=r"((r)[11]), \
          "=r"((r)[12]), "=r"((r)[13]), "=r"((r)[14]), "=r"((r)[15]), \
          "=r"((r)[16]), "=r"((r)[17]), "=r"((r)[18]), "=r"((r)[19]), \
          "=r"((r)[20]), "=r"((r)[21]), "=r"((r)[22]), "=r"((r)[23]), \
          "=r"((r)[24]), "=r"((r)[25]), "=r"((r)[26]), "=r"((r)[27]), \
          "=r"((r)[28]), "=r"((r)[29]), "=r"((r)[30]), "=r"((r)[31]) \
        : "r"(addr))

// SS-form bf16 MMA, cg1, fp32 accumulate in TMEM
__device__ __forceinline__ void mma_bf16_ss(uint32_t d, uint64_t ad, uint64_t bd,
                                            uint32_t idesc, uint32_t en) {
    asm volatile(
        "{\n\t.reg .pred p;\n\t"
        "setp.ne.u32 p, %5, 0;\n\t"
        "tcgen05.mma.cta_group::1.kind::f16 [%0], %1, %2, %3, {%4, %4, %4, %4}, p;\n\t}"
        :: "r"(d), "l"(ad), "l"(bd), "r"(idesc), "r"(0u), "r"(en) : "memory");
}

// idesc: dtype=F32, atype=btype=BF16, N=128, M=128, K-major both
#define MMA_IDESC ((1u<<4) | (1u<<7) | (1u<<10) | ((128u/8u)<<17) | ((128u/16u)<<24))

// SW128 K-major smem descriptor (LBO=1 (16B), SBO=64 (1024B), layout=SW128, Blackwell v1)
__device__ __forceinline__ uint64_t make_desc_sw128(uint32_t addr) {
    const uint64_t base =
        (uint64_t(2)  << 61) | (uint64_t(1) << 46) | (uint64_t(64) << 32) | (uint64_t(1) << 16);
    return base | ((uint64_t)(addr >> 4) & 0x3FFF);
}
#endif  // HAS_TCG

// ---------------- GEMM: C(2048x2304) = A(2048x768) @ B(2304x768)^T ----------
// A given pre-split as bf16 hi/lo. 3xbf16 emulation:
//   C = Ahi*Bhi + Ahi*Blo + Alo*Bhi  (fp32 TMEM accumulate)
// CTA tile: M=128, N=256 (two N=128 accumulators) -> grid (9,16)=144 CTAs, 1 wave.
#define KC      64                    // K elems per chunk (64 bf16 = 128B rows)
#define NCHUNK  (HH / KC)             // 12
#define TILEB   16384                 // 128 rows x 128B
#define STAGEB  (6 * TILEB)           // Ah, Al, Bh0, Bl0, Bh1, Bl1 = 96KB
#define GEMM_SMEM (1024 + 2 * STAGEB) // 197632 bytes

__global__ void __launch_bounds__(256, 1)
gemm_tc(const __nv_bfloat16* __restrict__ Ahg,
        const __nv_bfloat16* __restrict__ Alg,
        const __nv_bfloat16* __restrict__ Bhg,
        const __nv_bfloat16* __restrict__ Blg,
        float* __restrict__ C) {
#if HAS_TCG
    extern __shared__ char smem[];
    uint32_t sb = smem_u32(smem);
    int tid = threadIdx.x;
    int wid = tid >> 5, lane = tid & 31;

    // smem map: [0] tmem ptr, [16]/[24] mbarriers, tiles from 1024
    if (wid == 0) TC_ALLOC(sb, 512);
    if (tid == 0) { mbar_init(sb + 16, 1); mbar_init(sb + 24, 1); }
    __syncthreads();
    uint32_t tmem;
    asm volatile("ld.shared.b32 %0, [%1];" : "=r"(tmem) : "r"(sb));

    const __nv_bfloat16* Ahb = Ahg + (size_t)blockIdx.y * 128 * HH;
    const __nv_bfloat16* Alb = Alg + (size_t)blockIdx.y * 128 * HH;
    const __nv_bfloat16* Bhb = Bhg + (size_t)blockIdx.x * 256 * HH;
    const __nv_bfloat16* Blb = Blg + (size_t)blockIdx.x * 256 * HH;

    for (int i = 0; i < NCHUNK; i++) {
        int b = i & 1;
        char* sAh  = smem + 1024 + b * STAGEB;
        char* sAl  = sAh + TILEB;
        char* sBh0 = sAl + TILEB;
        char* sBl0 = sBh0 + TILEB;
        char* sBh1 = sBl0 + TILEB;
        char* sBl1 = sBh1 + TILEB;
        uint32_t bufu = sb + 1024 + b * STAGEB;

        if (i >= 2) mbar_wait(sb + 16 + 8 * b, ((i - 2) >> 1) & 1);

        int kc0 = i * KC;
        // A hi/lo: 128 rows x 64 bf16 each; 1024 16B-slots per part
        #pragma unroll
        for (int j = 0; j < 4; j++) {
            int u = tid + j * 256;
            int row = u >> 3, q = u & 7;
            size_t go = (size_t)row * HH + kc0 + q * 8;
            uint4 vh = *(const uint4*)(Ahb + go);
            uint4 vl = *(const uint4*)(Alb + go);
            uint32_t off = swz128(row * 128 + q * 16);
            *(uint4*)(sAh + off) = vh;
            *(uint4*)(sAl + off) = vl;
        }
        // B hi/lo for both N-blocks
        #pragma unroll
        for (int j = 0; j < 4; j++) {
            int u = tid + j * 256;
            int row = u >> 3, q = u & 7;
            size_t go0 = (size_t)row * HH + kc0 + q * 8;
            size_t go1 = (size_t)(row + 128) * HH + kc0 + q * 8;
            uint32_t off = swz128(row * 128 + q * 16);
            *(uint4*)(sBh0 + off) = *(const uint4*)(Bhb + go0);
            *(uint4*)(sBl0 + off) = *(const uint4*)(Blb + go0);
            *(uint4*)(sBh1 + off) = *(const uint4*)(Bhb + go1);
            *(uint4*)(sBl1 + off) = *(const uint4*)(Blb + go1);
        }
        FENCE_ASYNC_SHARED();
        __syncthreads();

        if (wid == 0 && elect_one()) {
            uint64_t dAh  = make_desc_sw128(bufu);
            uint64_t dAl  = make_desc_sw128(bufu + TILEB);
            uint64_t dBh0 = make_desc_sw128(bufu + 2 * TILEB);
            uint64_t dBl0 = make_desc_sw128(bufu + 3 * TILEB);
            uint64_t dBh1 = make_desc_sw128(bufu + 4 * TILEB);
            uint64_t dBl1 = make_desc_sw128(bufu + 5 * TILEB);
            uint32_t first = (i == 0) ? 0u : 1u;
            #pragma unroll
            for (int s = 0; s < 4; s++) {   // K=16 bf16 per MMA, +32B per step
                uint64_t o = (uint64_t)(s * 2);
                uint32_t en0 = (s == 0) ? first : 1u;
                mma_bf16_ss(tmem,       dAh + o, dBh0 + o, MMA_IDESC, en0);
                mma_bf16_ss(tmem,       dAh + o, dBl0 + o, MMA_IDESC, 1u);
                mma_bf16_ss(tmem,       dAl + o, dBh0 + o, MMA_IDESC, 1u);
                mma_bf16_ss(tmem + 128, dAh + o, dBh1 + o, MMA_IDESC, en0);
                mma_bf16_ss(tmem + 128, dAh + o, dBl1 + o, MMA_IDESC, 1u);
                mma_bf16_ss(tmem + 128, dAl + o, dBh1 + o, MMA_IDESC, 1u);
            }
            TC_COMMIT(sb + 16 + 8 * b);
        }
    }

    // drain: 6 commits per mbar; loop waits consumed up through the 5th -> wait 6th (parity 1)
    mbar_wait(sb + 16, 1);
    mbar_wait(sb + 24, 1);
    TC_FENCE_AFTER();

    // epilogue: 8 warps; warp w: rows (w&3)*32+lane, cols (w>>2)*128 .. +128
    int sub = wid & 3, half = wid >> 2;
    int rowg = blockIdx.y * 128 + sub * 32 + lane;
    float* crow = C + (size_t)rowg * G3 + blockIdx.x * 256 + half * 128;
    #pragma unroll
    for (int part = 0; part < 2; part++) {
        uint32_t r0[32], r1[32];
        TC_LD_X32(r0, tmem + half * 128 + part * 64);
        TC_LD_X32(r1, tmem + half * 128 + part * 64 + 32);
        TC_WAIT_LD();
        #pragma unroll
        for (int c = 0; c < 32; c += 4) {
            *(float4*)(crow + part * 64 + c) = make_float4(
                __uint_as_float(r0[c]), __uint_as_float(r0[c+1]),
                __uint_as_float(r0[c+2]), __uint_as_float(r0[c+3]));
            *(float4*)(crow + part * 64 + 32 + c) = make_float4(
                __uint_as_float(r1[c]), __uint_as_float(r1[c+1]),
                __uint_as_float(r1[c+2]), __uint_as_float(r1[c+3]));
        }
    }
    TC_FENCE_BEFORE();

    __syncthreads();
    if (tid == 0) { mbar_inval(sb + 16); mbar_inval(sb + 24); }
    __syncthreads();
    if (wid == 0) {
        TC_RELINQUISH();
        TC_DEALLOC(tmem, 512);
    }
#else
    // ---------------- FFMA fallback (plain sm_103 pass only; never selected
    // at runtime on GB300 — the driver loads the sm_103a cubin) --------------
    extern __shared__ char smem[];
    float* As = (float*)smem;              // [16][128]
    float* Bs = As + 16 * 128;             // [16][128]

    int tid = threadIdx.x;
    int ty = tid >> 4;
    int tx = tid & 15;

    const __nv_bfloat16* Ahb = Ahg + (size_t)blockIdx.y * 128 * HH;
    const __nv_bfloat16* Alb = Alg + (size_t)blockIdx.y * 128 * HH;

    for (int nb = 0; nb < 2; nb++) {
        const __nv_bfloat16* Bhb = Bhg + (size_t)(blockIdx.x * 256 + nb * 128) * HH;
        const __nv_bfloat16* Blb = Blg + (size_t)(blockIdx.x * 256 + nb * 128) * HH;

        float acc[8][8];
        #pragma unroll
        for (int i = 0; i < 8; i++)
            #pragma unroll
            for (int j = 0; j < 8; j++) acc[i][j] = 0.0f;

        for (int kt = 0; kt < HH; kt += 16) {
            {
                int r  = tid >> 1;
                int kq = (tid & 1) * 8;
                size_t go = (size_t)r * HH + kt + kq;
                uint4 vh = *(const uint4*)(Ahb + go);
                uint4 vl = *(const uint4*)(Alb + go);
                const __nv_bfloat16* ph = (const __nv_bfloat16*)&vh;
                const __nv_bfloat16* pl = (const __nv_bfloat16*)&vl;
                #pragma unroll
                for (int e = 0; e < 8; e++)
                    As[(kq + e) * 128 + r] = __bfloat162float(ph[e]) + __bfloat162float(pl[e]);
            }
            {
                int n  = tid >> 1;
                int kq = (tid & 1) * 8;
                size_t go = (size_t)n * HH + kt + kq;
                uint4 vh = *(const uint4*)(Bhb + go);
                uint4 vl = *(const uint4*)(Blb + go);
                const __nv_bfloat16* ph = (const __nv_bfloat16*)&vh;
                const __nv_bfloat16* pl = (const __nv_bfloat16*)&vl;
                #pragma unroll
                for (int e = 0; e < 8; e++)
                    Bs[(kq + e) * 128 + n] = __bfloat162float(ph[e]) + __bfloat162float(pl[e]);
            }
            __syncthreads();

            #pragma unroll
            for (int k = 0; k < 16; k++) {
                float ar[8], br[8];
                #pragma unroll
                for (int e = 0; e < 8; e++) ar[e] = As[k * 128 + ty * 8 + e];
                #pragma unroll
                for (int e = 0; e < 8; e++) br[e] = Bs[k * 128 + tx * 8 + e];
                #pragma unroll
                for (int i = 0; i < 8; i++)
                    #pragma unroll
                    for (int j = 0; j < 8; j++)
                        acc[i][j] = fmaf(ar[i], br[j], acc[i][j]);
            }
            __syncthreads();
        }

        int rowBase = blockIdx.y * 128 + ty * 8;
        int colBase = blockIdx.x * 256 + nb * 128 + tx * 8;
        #pragma unroll
        for (int i = 0; i < 8; i++) {
            *(float4*)(C + (size_t)(rowBase + i) * G3 + colBase) =
                make_float4(acc[i][0], acc[i][1], acc[i][2], acc[i][3]);
            *(float4*)(C + (size_t)(rowBase + i) * G3 + colBase + 4) =
                make_float4(acc[i][4], acc[i][5], acc[i][6], acc[i][7]);
        }
        __syncthreads();
    }
#endif
}

// ---------------- tiny utility kernels ----------------
__global__ void zero_kernel(float* p, int n) {
    int i = blockIdx.x * blockDim.x + threadIdx.x;
    if (i < n) p[i] = 0.0f;
}

// bf16 hi/lo split of a (G3 x HH) slice of a weight matrix
__global__ void conv_bf16(const float* __restrict__ W, int ld, int off,
                          __nv_bfloat16* __restrict__ hi, __nv_bfloat16* __restrict__ lo) {
    int idx = blockIdx.x * blockDim.x + threadIdx.x;
    if (idx >= G3 * HH) return;
    int j = idx / HH, k = idx % HH;
    float x = W[(size_t)j * ld + off + k];
    __nv_bfloat16 h = __float2bfloat16(x);
    hi[idx] = h;
    lo[idx] = __float2bfloat16(x - __bfloat162float(h));
}

// Fold embed() into Wih:  M[d][j] = SCALE * sum_e embW[e][d] * Wih[j][e]
//                         b[j]    = bih[j] + sum_e embB[e]  * Wih[j][e]
__global__ void prep_combined(const float* __restrict__ Wih, int ldw,
                              const float* __restrict__ bih,
                              const float* __restrict__ embW,
                              const float* __restrict__ embB,
                              float* __restrict__ Mout, float* __restrict__ bout) {
    int j = blockIdx.x * blockDim.x + threadIdx.x;
    if (j >= G3) return;
    float accM[DD];
    #pragma unroll
    for (int d = 0; d < DD; d++) accM[d] = 0.0f;
    float accb = 0.0f;
    const float* wrow = Wih + (size_t)j * ldw;
    for (int e = 0; e < EE; e++) {
        float w = wrow[e];
        accb += embB[e] * w;
        const float* er = embW + e * DD;
        #pragma unroll
        for (int d = 0; d < DD; d++) accM[d] += er[d] * w;
    }
    #pragma unroll
    for (int d = 0; d < DD; d++) Mout[d * G3 + j] = SCALEF * accM[d];
    bout[j] = accb + bih[j];
}

// ---------------- fused GRU update (velocity sub fused; writes h + bf16 split) ----
__global__ void gru_update(const float* __restrict__ Mm, const float* __restrict__ bvec,
                           const float* __restrict__ bhh, const float* __restrict__ C2,
                           const float* __restrict__ G,
                           const float* __restrict__ pa, const float* __restrict__ pb,
                           float* __restrict__ h,
                           __nv_bfloat16* __restrict__ ah, __nv_bfloat16* __restrict__ al) {
    int j = blockIdx.x * blockDim.x + threadIdx.x;   // 0..767
    int row = blockIdx.y;

    __shared__ float vs[DD];
    if (threadIdx.x < DD)
        vs[threadIdx.x] = pa[row * DD + threadIdx.x] - pb[row * DD + threadIdx.x];
    __syncthreads();

    float gi_r = bvec[j];
    float gi_z = bvec[j + HH];
    float gi_n = bvec[j + 2 * HH];
    #pragma unroll
    for (int d = 0; d < DD; d++) {
        float vd = vs[d];
        gi_r = fmaf(vd, Mm[d * G3 + j],          gi_r);
        gi_z = fmaf(vd, Mm[d * G3 + j + HH],     gi_z);
        gi_n = fmaf(vd, Mm[d * G3 + j + 2 * HH], gi_n);
    }
    if (C2 != nullptr) {
        const float* c = C2 + (size_t)row * G3;
        gi_r += c[j];
        gi_z += c[j + HH];
        gi_n += c[j + 2 * HH];
    }
    float gh_r, gh_z, gh_n;
    if (G != nullptr) {
        const float* grow = G + (size_t)row * G3;
        gh_r = grow[j]          + bhh[j];
        gh_z = grow[j + HH]     + bhh[j + HH];
        gh_n = grow[j + 2 * HH] + bhh[j + 2 * HH];
    } else {
        gh_r = bhh[j];
        gh_z = bhh[j + HH];
        gh_n = bhh[j + 2 * HH];
    }

    float r = 1.0f / (1.0f + expf(-(gi_r + gh_r)));
    float z = 1.0f / (1.0f + expf(-(gi_z + gh_z)));
    float n = tanhf(gi_n + r * gh_n);
    size_t idx = (size_t)row * HH + j;
    float ho = h[idx];
    float hn = (1.0f - z) * n + z * ho;
    h[idx] = hn;
    __nv_bfloat16 hb = __float2bfloat16(hn);
    ah[idx] = hb;
    al[idx] = __float2bfloat16(hn - __bfloat162float(hb));
}

// ---------------- decoder head: h2n + mix + relu + pos ----------------
__global__ void h2n_pos(const float* __restrict__ h,
                        const float* __restrict__ h2nW, const float* __restrict__ h2nB,
                        const float* __restrict__ mixW, const float* __restrict__ mixB,
                        const float* __restrict__ base,
                        float* __restrict__ out_rel, float* __restrict__ out_pos) {
    int row = blockIdx.x;
    int tid = threadIdx.x;
    int warp = tid >> 5, lane = tid & 31;
    __shared__ float sn[5];

    if (warp < 5) {
        const float* hr = h + (size_t)row * HH;
        const float* wr = h2nW + warp * HH;
        float s = 0.0f;
        for (int i = lane; i < HH; i += 32) s = fmaf(hr[i], wr[i], s);
        #pragma unroll
        for (int o = 16; o > 0; o >>= 1) s += __shfl_down_sync(0xffffffffu, s, o);
        if (lane == 0) {
            float raw = s + h2nB[warp];
            float val;
            if (warp < 2) {
                val = raw;
            } else if (warp < 4) {
                float sp = raw > 0.0f ? raw + log1pf(expf(-raw)) : log1pf(expf(raw));
                val = 0.01f + 0.2f * sp;
            } else {
                val = 0.7f * tanhf(raw);
            }
            sn[warp] = val;
            out_rel[(size_t)row * 5 + warp] = val;
        }
    }
    __syncthreads();
    if (tid < DD) {
        float acc = mixB[tid];
        #pragma unroll
        for (int c = 0; c < 5; c++) acc = fmaf(sn[c], mixW[tid * 5 + c], acc);
        acc = acc > 0.0f ? acc : 0.0f;
        out_pos[(size_t)row * DD + tid] = base[(size_t)row * DD + tid] + acc;
    }
}

// ---------------- host orchestration ----------------
extern "C" void kernel_launch(void* const* d_in, const int* in_sizes, int n_in,
                              void* d_out, int out_size) {
    const float* observed = (const float*)d_in[0];
    const float* emb_W    = (const float*)d_in[1];
    const float* emb_b    = (const float*)d_in[2];
    const float* e1_Wih   = (const float*)d_in[3];
    const float* e1_Whh   = (const float*)d_in[4];
    const float* e1_bih   = (const float*)d_in[5];
    const float* e1_bhh   = (const float*)d_in[6];
    const float* e2_Wih   = (const float*)d_in[7];
    const float* e2_Whh   = (const float*)d_in[8];
    const float* e2_bih   = (const float*)d_in[9];
    const float* e2_bhh   = (const float*)d_in[10];
    const float* dec_Wih  = (const float*)d_in[11];
    const float* dec_Whh  = (const float*)d_in[12];
    const float* dec_bih  = (const float*)d_in[13];
    const float* dec_bhh  = (const float*)d_in[14];
    const float* h2n_W    = (const float*)d_in[15];
    const float* h2n_b    = (const float*)d_in[16];
    const float* mix_W    = (const float*)d_in[17];
    const float* mix_b    = (const float*)d_in[18];
    float* out = (float*)d_out;

    float *M1, *M2, *Md, *b1, *b2, *bd, *C2, *G, *h;
    __nv_bfloat16 *Bh1, *Bl1, *Bh2, *Bl2, *Bhd, *Bld, *Bh2x, *Bl2x, *Ah, *Al;
    cudaGetSymbolAddress((void**)&M1,  g_M1);
    cudaGetSymbolAddress((void**)&M2,  g_M2);
    cudaGetSymbolAddress((void**)&Md,  g_Md);
    cudaGetSymbolAddress((void**)&b1,  g_b1);
    cudaGetSymbolAddress((void**)&b2,  g_b2);
    cudaGetSymbolAddress((void**)&bd,  g_bd);
    cudaGetSymbolAddress((void**)&Bh1, g_Bh1);
    cudaGetSymbolAddress((void**)&Bl1, g_Bl1);
    cudaGetSymbolAddress((void**)&Bh2, g_Bh2);
    cudaGetSymbolAddress((void**)&Bl2, g_Bl2);
    cudaGetSymbolAddress((void**)&Bhd, g_Bhd);
    cudaGetSymbolAddress((void**)&Bld, g_Bld);
    cudaGetSymbolAddress((void**)&Bh2x,g_Bh2x);
    cudaGetSymbolAddress((void**)&Bl2x,g_Bl2x);
    cudaGetSymbolAddress((void**)&Ah,  g_Ah);
    cudaGetSymbolAddress((void**)&Al,  g_Al);
    cudaGetSymbolAddress((void**)&C2,  g_C2);
    cudaGetSymbolAddress((void**)&G,   g_G);
    cudaGetSymbolAddress((void**)&h,   g_h);

    cudaFuncSetAttribute(gemm_tc, cudaFuncAttributeMaxDynamicSharedMemorySize, GEMM_SMEM);

    const int ND = NB * DD;           // 32768
    const int NH = NB * HH;           // 1572864
    float* rel_out  = out;                          // (12, 2048, 5)
    float* pred_out = out + (size_t)NPRED * NB * 5; // (12, 2048, 16)

    dim3 gemmGrid(G3 / 256, NB / 128);   // (9, 16) = 144 CTAs = 1 wave
    dim3 gruGrid(HH / 256, NB);          // (3, 2048)
    const int WELEM = G3 * HH;

    // ---- one-time prep (per call; deterministic) ----
    prep_combined<<<(G3 + 255) / 256, 256>>>(e1_Wih,  EE,      e1_bih,  emb_W, emb_b, M1, b1);
    prep_combined<<<(G3 + 255) / 256, 256>>>(e2_Wih,  EE + HH, e2_bih,  emb_W, emb_b, M2, b2);
    prep_combined<<<(G3 + 255) / 256, 256>>>(dec_Wih, EE,      dec_bih, emb_W, emb_b, Md, bd);

    conv_bf16<<<(WELEM + 255) / 256, 256>>>(e1_Whh,  HH,      0,  Bh1,  Bl1);
    conv_bf16<<<(WELEM + 255) / 256, 256>>>(e2_Whh,  HH,      0,  Bh2,  Bl2);
    conv_bf16<<<(WELEM + 255) / 256, 256>>>(dec_Whh, HH,      0,  Bhd,  Bld);
    conv_bf16<<<(WELEM + 255) / 256, 256>>>(e2_Wih,  EE + HH, EE, Bh2x, Bl2x);

    zero_kernel<<<(NH + 255) / 256, 256>>>(h, NH);

    // ---- encoder 1: backward velocities vel_b[t] = obs[7-t] - obs[6-t] ----
    for (int t = 0; t < TT - 1; t++) {
        const float* pa = observed + (size_t)(7 - t) * ND;
        const float* pb = observed + (size_t)(6 - t) * ND;
        const float* Gp = nullptr;
        if (t > 0) {   // t==0: h==0 -> gh==0
            gemm_tc<<<gemmGrid, 256, GEMM_SMEM>>>(Ah, Al, Bh1, Bl1, G);
            Gp = G;
        }
        gru_update<<<gruGrid, 256>>>(M1, b1, e1_bhh, nullptr, Gp, pa, pb, h, Ah, Al);
    }

    // constant enc2 input contribution: C2 = h_inv @ e2_Wih[:,256:]^T
    // (Ah/Al currently hold the split of h_inv)
    gemm_tc<<<gemmGrid, 256, GEMM_SMEM>>>(Ah, Al, Bh2x, Bl2x, C2);

    zero_kernel<<<(NH + 255) / 256, 256>>>(h, NH);

    // ---- encoder 2: forward velocities vel_f[t] = obs[t+1] - obs[t] ----
    for (int t = 0; t < TT - 1; t++) {
        const float* pa = observed + (size_t)(t + 1) * ND;
        const float* pb = observed + (size_t)t * ND;
        const float* Gp = nullptr;
        if (t > 0) {
            gemm_tc<<<gemmGrid, 256, GEMM_SMEM>>>(Ah, Al, Bh2, Bl2, G);
            Gp = G;
        }
        gru_update<<<gruGrid, 256>>>(M2, b2, e2_bhh, C2, Gp, pa, pb, h, Ah, Al);
    }

    // ---- decoder: 12 autoregressive steps ----
    for (int k = 0; k < NPRED; k++) {
        const float *pa, *pb;
        if (k == 0) {
            pa = observed + (size_t)7 * ND;
            pb = observed + (size_t)6 * ND;
        } else if (k == 1) {
            pa = pred_out;                        // p0
            pb = observed + (size_t)7 * ND;
        } else {
            pa = pred_out + (size_t)(k - 1) * ND; // p_{k-1}
            pb = pred_out + (size_t)(k - 2) * ND; // p_{k-2}
        }
        gemm_tc<<<gemmGrid, 256, GEMM_SMEM>>>(Ah, Al, Bhd, Bld, G);
        gru_update<<<gruGrid, 256>>>(Md, bd, dec_bhh, nullptr, G, pa, pb, h, Ah, Al);
        h2n_pos<<<NB, 160>>>(h, h2n_W, h2n_b, mix_W, mix_b, pa,
                             rel_out + (size_t)k * NB * 5,
                             pred_out + (size_t)k * ND);
    }
}

// round 5
// speedup vs baseline: 3.2139x; 1.0007x over previous
#include <cuda_runtime.h>
#include <cuda_bf16.h>
#include <cstdint>
#include <math.h>

// Problem constants (dataset-fixed: T=8, N=2048, E=256, H=768, D=16, n_predict=12)
#define NB    2048
#define DD    16
#define EE    256
#define HH    768
#define G3    2304        // 3*H
#define TT    8
#define NPRED 12
#define SCALEF 4.0f

// tcgen05 is only legal in the arch-SPECIFIC (sm_103a / sm_100a) device pass.
// The harness also runs a plain sm_103 pass (same __CUDA_ARCH__!), so gate on
// the accelerated-feature macros only.
#if defined(__CUDA_ARCH_FEAT_SM103_ALL) || defined(__CUDA_ARCH_FEAT_SM100_ALL) || \
    (defined(__CUDA_ARCH_SPECIFIC__) && (__CUDA_ARCH_SPECIFIC__ >= 1000))
#define HAS_TCG 1
#else
#define HAS_TCG 0
#endif

// ---------------- device scratch (no allocations allowed) ----------------
__device__ __align__(256) float g_M1[DD*G3];
__device__ __align__(256) float g_M2[DD*G3];
__device__ __align__(256) float g_Md[DD*G3];
__device__ __align__(256) float g_b1[G3];
__device__ __align__(256) float g_b2[G3];
__device__ __align__(256) float g_bd[G3];
__device__ __align__(256) __nv_bfloat16 g_Bh1[G3*HH];   // e1_Whh hi/lo
__device__ __align__(256) __nv_bfloat16 g_Bl1[G3*HH];
__device__ __align__(256) __nv_bfloat16 g_Bh2[G3*HH];   // e2_Whh
__device__ __align__(256) __nv_bfloat16 g_Bl2[G3*HH];
__device__ __align__(256) __nv_bfloat16 g_Bhd[G3*HH];   // dec_Whh
__device__ __align__(256) __nv_bfloat16 g_Bld[G3*HH];
__device__ __align__(256) __nv_bfloat16 g_Bh2x[G3*HH];  // e2_Wih[:,256:]
__device__ __align__(256) __nv_bfloat16 g_Bl2x[G3*HH];
__device__ __align__(256) __nv_bfloat16 g_Ah[NB*HH];    // h split hi/lo (GEMM A operand)
__device__ __align__(256) __nv_bfloat16 g_Al[NB*HH];
__device__ __align__(256) float g_C2[NB*G3];    // h_inv @ e2_Wih[:,256:]^T
__device__ __align__(256) float g_G[NB*G3];     // gh buffer
__device__ __align__(256) float g_h[NB*HH];

// ---------------- small PTX helpers ----------------
__device__ __forceinline__ uint32_t smem_u32(const void* p) {
    uint32_t a;
    asm("{ .reg .u64 t; cvta.to.shared.u64 t, %1; cvt.u32.u64 %0, t; }"
        : "=r"(a) : "l"(p));
    return a;
}

__device__ __forceinline__ uint32_t elect_one() {
    uint32_t pred;
    asm volatile(
        "{\n\t.reg .pred p;\n\t"
        "elect.sync _|p, 0xFFFFFFFF;\n\t"
        "selp.b32 %0, 1, 0, p;\n\t}"
        : "=r"(pred));
    return pred;
}

__device__ __forceinline__ void mbar_init(uint32_t mbar, uint32_t cnt) {
    asm volatile("mbarrier.init.shared.b64 [%0], %1;" :: "r"(mbar), "r"(cnt) : "memory");
}
__device__ __forceinline__ void mbar_inval(uint32_t mbar) {
    asm volatile("mbarrier.inval.shared.b64 [%0];" :: "r"(mbar) : "memory");
}
__device__ __forceinline__ void mbar_wait(uint32_t mbar, uint32_t parity) {
    uint32_t done;
    asm volatile(
        "{\n\t.reg .pred p;\n\t"
        "mbarrier.try_wait.parity.acquire.cta.shared::cta.b64 p, [%1], %2;\n\t"
        "selp.b32 %0, 1, 0, p;\n\t}"
        : "=r"(done) : "r"(mbar), "r"(parity) : "memory");
    while (!done) {
        asm volatile(
            "{\n\t.reg .pred p;\n\t"
            "mbarrier.try_wait.parity.acquire.cta.shared::cta.b64 p, [%1], %2, 0x989680;\n\t"
            "selp.b32 %0, 1, 0, p;\n\t}"
            : "=r"(done) : "r"(mbar), "r"(parity) : "memory");
    }
}

#define FENCE_ASYNC_SHARED() asm volatile("fence.proxy.async.shared::cta;" ::: "memory")

__device__ __forceinline__ uint32_t swz128(uint32_t off) {
    return off ^ ((off >> 3) & 0x70);
}

#if HAS_TCG
// ------- tcgen05-only macros (compiled exclusively in the sm_103a pass) -------
#define TC_ALLOC(smem_addr, n) \
    asm volatile("tcgen05.alloc.cta_group::1.sync.aligned.shared::cta.b32 [%0], %1;" \
                 :: "r"(smem_addr), "r"((uint32_t)(n)) : "memory")
#define TC_DEALLOC(tmem_addr, n) \
    asm volatile("tcgen05.dealloc.cta_group::1.sync.aligned.b32 %0, %1;" \
                 :: "r"(tmem_addr), "r"((uint32_t)(n)))
#define TC_RELINQUISH() \
    asm volatile("tcgen05.relinquish_alloc_permit.cta_group::1.sync.aligned;")
#define TC_COMMIT(mbar) \
    asm volatile("tcgen05.commit.cta_group::1.mbarrier::arrive::one.shared::cluster.b64 [%0];" \
                 :: "r"(mbar) : "memory")
#define TC_FENCE_AFTER()  asm volatile("tcgen05.fence::after_thread_sync;" ::: "memory")
#define TC_FENCE_BEFORE() asm volatile("tcgen05.fence::before_thread_sync;" ::: "memory")
#define TC_WAIT_LD()      asm volatile("tcgen05.wait::ld.sync.aligned;" ::: "memory")

#define TC_LD_X32(r, addr) \
    asm volatile( \
        "tcgen05.ld.sync.aligned.32x32b.x32.b32 " \
        "{%0, %1, %2, %3, %4, %5, %6, %7, " \
        " %8, %9, %10, %11, %12, %13, %14, %15, " \
        " %16, %17, %18, %19, %20, %21, %22, %23, " \
        " %24, %25, %26, %27, %28, %29, %30, %31}, [%32];" \
        : "=r"((r)[0]),  "=r"((r)[1]),  "=r"((r)[2]),  "=r"((r)[3]), \
          "=r"((r)[4]),  "=r"((r)[5]),  "=r"((r)[6]),  "=r"((r)[7]), \
          "=r"((r)[8]),  "=r"((r)[9]),  "=r"((r)[10]), "=r"((r)[11]), \
          "=r"((r)[12]), "=r"((r)[13]), "=r"((r)[14]), "=r"((r)[15]), \
          "=r"((r)[16]), "=r"((r)[17]), "=r"((r)[18]), "=r"((r)[19]), \
          "=r"((r)[20]), "=r"((r)[21]), "=r"((r)[22]), "=r"((r)[23]), \
          "=r"((r)[24]), "=r"((r)[25]), "=r"((r)[26]), "=r"((r)[27]), \
          "=r"((r)[28]), "=r"((r)[29]), "=r"((r)[30]), "=r"((r)[31]) \
        : "r"(addr))

// SS-form bf16 MMA, cg1, fp32 accumulate in TMEM
__device__ __forceinline__ void mma_bf16_ss(uint32_t d, uint64_t ad, uint64_t bd,
                                            uint32_t idesc, uint32_t en) {
    asm volatile(
        "{\n\t.reg .pred p;\n\t"
        "setp.ne.u32 p, %5, 0;\n\t"
        "tcgen05.mma.cta_group::1.kind::f16 [%0], %1, %2, %3, {%4, %4, %4, %4}, p;\n\t}"
        :: "r"(d), "l"(ad), "l"(bd), "r"(idesc), "r"(0u), "r"(en) : "memory");
}

// idesc: dtype=F32, atype=btype=BF16, N=128, M=128, K-major both
#define MMA_IDESC ((1u<<4) | (1u<<7) | (1u<<10) | ((128u/8u)<<17) | ((128u/16u)<<24))

// SW128 K-major smem descriptor (LBO=1 (16B), SBO=64 (1024B), layout=SW128, Blackwell v1)
__device__ __forceinline__ uint64_t make_desc_sw128(uint32_t addr) {
    const uint64_t base =
        (uint64_t(2)  << 61) | (uint64_t(1) << 46) | (uint64_t(64) << 32) | (uint64_t(1) << 16);
    return base | ((uint64_t)(addr >> 4) & 0x3FFF);
}
#endif  // HAS_TCG

// ---------------- GEMM: C(2048x2304) = A(2048x768) @ B(2304x768)^T ----------
// A given pre-split as bf16 hi/lo. 3xbf16 emulation:
//   C = Ahi*Bhi + Ahi*Blo + Alo*Bhi  (fp32 TMEM accumulate)
// CTA tile: M=128, N=256 (two N=128 accumulators) -> grid (9,16)=144 CTAs, 1 wave.
#define KC      64                    // K elems per chunk (64 bf16 = 128B rows)
#define NCHUNK  (HH / KC)             // 12
#define TILEB   16384                 // 128 rows x 128B
#define STAGEB  (6 * TILEB)           // Ah, Al, Bh0, Bl0, Bh1, Bl1 = 96KB
#define GEMM_SMEM (1024 + 2 * STAGEB) // 197632 bytes

__global__ void __launch_bounds__(256, 1)
gemm_tc(const __nv_bfloat16* __restrict__ Ahg,
        const __nv_bfloat16* __restrict__ Alg,
        const __nv_bfloat16* __restrict__ Bhg,
        const __nv_bfloat16* __restrict__ Blg,
        float* __restrict__ C) {
#if HAS_TCG
    extern __shared__ char smem[];
    uint32_t sb = smem_u32(smem);
    int tid = threadIdx.x;
    int wid = tid >> 5, lane = tid & 31;

    // smem map: [0] tmem ptr, [16]/[24] mbarriers, tiles from 1024
    if (wid == 0) TC_ALLOC(sb, 512);
    if (tid == 0) { mbar_init(sb + 16, 1); mbar_init(sb + 24, 1); }
    __syncthreads();
    uint32_t tmem;
    asm volatile("ld.shared.b32 %0, [%1];" : "=r"(tmem) : "r"(sb));

    const __nv_bfloat16* Ahb = Ahg + (size_t)blockIdx.y * 128 * HH;
    const __nv_bfloat16* Alb = Alg + (size_t)blockIdx.y * 128 * HH;
    const __nv_bfloat16* Bhb = Bhg + (size_t)blockIdx.x * 256 * HH;
    const __nv_bfloat16* Blb = Blg + (size_t)blockIdx.x * 256 * HH;

    for (int i = 0; i < NCHUNK; i++) {
        int b = i & 1;
        char* sAh  = smem + 1024 + b * STAGEB;
        char* sAl  = sAh + TILEB;
        char* sBh0 = sAl + TILEB;
        char* sBl0 = sBh0 + TILEB;
        char* sBh1 = sBl0 + TILEB;
        char* sBl1 = sBh1 + TILEB;
        uint32_t bufu = sb + 1024 + b * STAGEB;

        if (i >= 2) mbar_wait(sb + 16 + 8 * b, ((i - 2) >> 1) & 1);

        int kc0 = i * KC;
        // A hi/lo: 128 rows x 64 bf16 each; 1024 16B-slots per part
        #pragma unroll
        for (int j = 0; j < 4; j++) {
            int u = tid + j * 256;
            int row = u >> 3, q = u & 7;
            size_t go = (size_t)row * HH + kc0 + q * 8;
            uint4 vh = *(const uint4*)(Ahb + go);
            uint4 vl = *(const uint4*)(Alb + go);
            uint32_t off = swz128(row * 128 + q * 16);
            *(uint4*)(sAh + off) = vh;
            *(uint4*)(sAl + off) = vl;
        }
        // B hi/lo for both N-blocks
        #pragma unroll
        for (int j = 0; j < 4; j++) {
            int u = tid + j * 256;
            int row = u >> 3, q = u & 7;
            size_t go0 = (size_t)row * HH + kc0 + q * 8;
            size_t go1 = (size_t)(row + 128) * HH + kc0 + q * 8;
            uint32_t off = swz128(row * 128 + q * 16);
            *(uint4*)(sBh0 + off) = *(const uint4*)(Bhb + go0);
            *(uint4*)(sBl0 + off) = *(const uint4*)(Blb + go0);
            *(uint4*)(sBh1 + off) = *(const uint4*)(Bhb + go1);
            *(uint4*)(sBl1 + off) = *(const uint4*)(Blb + go1);
        }
        FENCE_ASYNC_SHARED();
        __syncthreads();

        if (wid == 0 && elect_one()) {
            uint64_t dAh  = make_desc_sw128(bufu);
            uint64_t dAl  = make_desc_sw128(bufu + TILEB);
            uint64_t dBh0 = make_desc_sw128(bufu + 2 * TILEB);
            uint64_t dBl0 = make_desc_sw128(bufu + 3 * TILEB);
            uint64_t dBh1 = make_desc_sw128(bufu + 4 * TILEB);
            uint64_t dBl1 = make_desc_sw128(bufu + 5 * TILEB);
            uint32_t first = (i == 0) ? 0u : 1u;
            #pragma unroll
            for (int s = 0; s < 4; s++) {   // K=16 bf16 per MMA, +32B per step
                uint64_t o = (uint64_t)(s * 2);
                uint32_t en0 = (s == 0) ? first : 1u;
                mma_bf16_ss(tmem,       dAh + o, dBh0 + o, MMA_IDESC, en0);
                mma_bf16_ss(tmem,       dAh + o, dBl0 + o, MMA_IDESC, 1u);
                mma_bf16_ss(tmem,       dAl + o, dBh0 + o, MMA_IDESC, 1u);
                mma_bf16_ss(tmem + 128, dAh + o, dBh1 + o, MMA_IDESC, en0);
                mma_bf16_ss(tmem + 128, dAh + o, dBl1 + o, MMA_IDESC, 1u);
                mma_bf16_ss(tmem + 128, dAl + o, dBh1 + o, MMA_IDESC, 1u);
            }
            TC_COMMIT(sb + 16 + 8 * b);
        }
    }

    // drain: 6 commits per mbar; loop waits consumed up through the 5th -> wait 6th (parity 1)
    mbar_wait(sb + 16, 1);
    mbar_wait(sb + 24, 1);
    TC_FENCE_AFTER();

    // epilogue: 8 warps; warp w: rows (w&3)*32+lane, cols (w>>2)*128 .. +128
    int sub = wid & 3, half = wid >> 2;
    int rowg = blockIdx.y * 128 + sub * 32 + lane;
    float* crow = C + (size_t)rowg * G3 + blockIdx.x * 256 + half * 128;
    #pragma unroll
    for (int part = 0; part < 2; part++) {
        uint32_t r0[32], r1[32];
        TC_LD_X32(r0, tmem + half * 128 + part * 64);
        TC_LD_X32(r1, tmem + half * 128 + part * 64 + 32);
        TC_WAIT_LD();
        #pragma unroll
        for (int c = 0; c < 32; c += 4) {
            *(float4*)(crow + part * 64 + c) = make_float4(
                __uint_as_float(r0[c]), __uint_as_float(r0[c+1]),
                __uint_as_float(r0[c+2]), __uint_as_float(r0[c+3]));
            *(float4*)(crow + part * 64 + 32 + c) = make_float4(
                __uint_as_float(r1[c]), __uint_as_float(r1[c+1]),
                __uint_as_float(r1[c+2]), __uint_as_float(r1[c+3]));
        }
    }
    TC_FENCE_BEFORE();

    __syncthreads();
    if (tid == 0) { mbar_inval(sb + 16); mbar_inval(sb + 24); }
    __syncthreads();
    if (wid == 0) {
        TC_RELINQUISH();
        TC_DEALLOC(tmem, 512);
    }
#else
    // ---------------- FFMA fallback (plain sm_103 pass only; never selected
    // at runtime on GB300 — the driver loads the sm_103a cubin) --------------
    extern __shared__ char smem[];
    float* As = (float*)smem;              // [16][128]
    float* Bs = As + 16 * 128;             // [16][128]

    int tid = threadIdx.x;
    int ty = tid >> 4;
    int tx = tid & 15;

    const __nv_bfloat16* Ahb = Ahg + (size_t)blockIdx.y * 128 * HH;
    const __nv_bfloat16* Alb = Alg + (size_t)blockIdx.y * 128 * HH;

    for (int nb = 0; nb < 2; nb++) {
        const __nv_bfloat16* Bhb = Bhg + (size_t)(blockIdx.x * 256 + nb * 128) * HH;
        const __nv_bfloat16* Blb = Blg + (size_t)(blockIdx.x * 256 + nb * 128) * HH;

        float acc[8][8];
        #pragma unroll
        for (int i = 0; i < 8; i++)
            #pragma unroll
            for (int j = 0; j < 8; j++) acc[i][j] = 0.0f;

        for (int kt = 0; kt < HH; kt += 16) {
            {
                int r  = tid >> 1;
                int kq = (tid & 1) * 8;
                size_t go = (size_t)r * HH + kt + kq;
                uint4 vh = *(const uint4*)(Ahb + go);
                uint4 vl = *(const uint4*)(Alb + go);
                const __nv_bfloat16* ph = (const __nv_bfloat16*)&vh;
                const __nv_bfloat16* pl = (const __nv_bfloat16*)&vl;
                #pragma unroll
                for (int e = 0; e < 8; e++)
                    As[(kq + e) * 128 + r] = __bfloat162float(ph[e]) + __bfloat162float(pl[e]);
            }
            {
                int n  = tid >> 1;
                int kq = (tid & 1) * 8;
                size_t go = (size_t)n * HH + kt + kq;
                uint4 vh = *(const uint4*)(Bhb + go);
                uint4 vl = *(const uint4*)(Blb + go);
                const __nv_bfloat16* ph = (const __nv_bfloat16*)&vh;
                const __nv_bfloat16* pl = (const __nv_bfloat16*)&vl;
                #pragma unroll
                for (int e = 0; e < 8; e++)
                    Bs[(kq + e) * 128 + n] = __bfloat162float(ph[e]) + __bfloat162float(pl[e]);
            }
            __syncthreads();

            #pragma unroll
            for (int k = 0; k < 16; k++) {
                float ar[8], br[8];
                #pragma unroll
                for (int e = 0; e < 8; e++) ar[e] = As[k * 128 + ty * 8 + e];
                #pragma unroll
                for (int e = 0; e < 8; e++) br[e] = Bs[k * 128 + tx * 8 + e];
                #pragma unroll
                for (int i = 0; i < 8; i++)
                    #pragma unroll
                    for (int j = 0; j < 8; j++)
                        acc[i][j] = fmaf(ar[i], br[j], acc[i][j]);
            }
            __syncthreads();
        }

        int rowBase = blockIdx.y * 128 + ty * 8;
        int colBase = blockIdx.x * 256 + nb * 128 + tx * 8;
        #pragma unroll
        for (int i = 0; i < 8; i++) {
            *(float4*)(C + (size_t)(rowBase + i) * G3 + colBase) =
                make_float4(acc[i][0], acc[i][1], acc[i][2], acc[i][3]);
            *(float4*)(C + (size_t)(rowBase + i) * G3 + colBase + 4) =
                make_float4(acc[i][4], acc[i][5], acc[i][6], acc[i][7]);
        }
        __syncthreads();
    }
#endif
}

// ---------------- tiny utility kernels ----------------
__global__ void zero_kernel(float* p, int n) {
    int i = blockIdx.x * blockDim.x + threadIdx.x;
    if (i < n) p[i] = 0.0f;
}

// bf16 hi/lo split of a (G3 x HH) slice of a weight matrix
__global__ void conv_bf16(const float* __restrict__ W, int ld, int off,
                          __nv_bfloat16* __restrict__ hi, __nv_bfloat16* __restrict__ lo) {
    int idx = blockIdx.x * blockDim.x + threadIdx.x;
    if (idx >= G3 * HH) return;
    int j = idx / HH, k = idx % HH;
    float x = W[(size_t)j * ld + off + k];
    __nv_bfloat16 h = __float2bfloat16(x);
    hi[idx] = h;
    lo[idx] = __float2bfloat16(x - __bfloat162float(h));
}

// Fold embed() into Wih:  M[d][j] = SCALE * sum_e embW[e][d] * Wih[j][e]
//                         b[j]    = bih[j] + sum_e embB[e]  * Wih[j][e]
__global__ void prep_combined(const float* __restrict__ Wih, int ldw,
                              const float* __restrict__ bih,
                              const float* __restrict__ embW,
                              const float* __restrict__ embB,
                              float* __restrict__ Mout, float* __restrict__ bout) {
    int j = blockIdx.x * blockDim.x + threadIdx.x;
    if (j >= G3) return;
    float accM[DD];
    #pragma unroll
    for (int d = 0; d < DD; d++) accM[d] = 0.0f;
    float accb = 0.0f;
    const float* wrow = Wih + (size_t)j * ldw;
    for (int e = 0; e < EE; e++) {
        float w = wrow[e];
        accb += embB[e] * w;
        const float* er = embW + e * DD;
        #pragma unroll
        for (int d = 0; d < DD; d++) accM[d] += er[d] * w;
    }
    #pragma unroll
    for (int d = 0; d < DD; d++) Mout[d * G3 + j] = SCALEF * accM[d];
    bout[j] = accb + bih[j];
}

// ---------------- fused GRU update (velocity sub fused; writes h + bf16 split) ----
__global__ void gru_update(const float* __restrict__ Mm, const float* __restrict__ bvec,
                           const float* __restrict__ bhh, const float* __restrict__ C2,
                           const float* __restrict__ G,
                           const float* __restrict__ pa, const float* __restrict__ pb,
                           float* __restrict__ h,
                           __nv_bfloat16* __restrict__ ah, __nv_bfloat16* __restrict__ al) {
    int j = blockIdx.x * blockDim.x + threadIdx.x;   // 0..767
    int row = blockIdx.y;

    __shared__ float vs[DD];
    if (threadIdx.x < DD)
        vs[threadIdx.x] = pa[row * DD + threadIdx.x] - pb[row * DD + threadIdx.x];
    __syncthreads();

    float gi_r = bvec[j];
    float gi_z = bvec[j + HH];
    float gi_n = bvec[j + 2 * HH];
    #pragma unroll
    for (int d = 0; d < DD; d++) {
        float vd = vs[d];
        gi_r = fmaf(vd, Mm[d * G3 + j],          gi_r);
        gi_z = fmaf(vd, Mm[d * G3 + j + HH],     gi_z);
        gi_n = fmaf(vd, Mm[d * G3 + j + 2 * HH], gi_n);
    }
    if (C2 != nullptr) {
        const float* c = C2 + (size_t)row * G3;
        gi_r += c[j];
        gi_z += c[j + HH];
        gi_n += c[j + 2 * HH];
    }
    float gh_r, gh_z, gh_n;
    if (G != nullptr) {
        const float* grow = G + (size_t)row * G3;
        gh_r = grow[j]          + bhh[j];
        gh_z = grow[j + HH]     + bhh[j + HH];
        gh_n = grow[j + 2 * HH] + bhh[j + 2 * HH];
    } else {
        gh_r = bhh[j];
        gh_z = bhh[j + HH];
        gh_n = bhh[j + 2 * HH];
    }

    float r = 1.0f / (1.0f + expf(-(gi_r + gh_r)));
    float z = 1.0f / (1.0f + expf(-(gi_z + gh_z)));
    float n = tanhf(gi_n + r * gh_n);
    size_t idx = (size_t)row * HH + j;
    float ho = h[idx];
    float hn = (1.0f - z) * n + z * ho;
    h[idx] = hn;
    __nv_bfloat16 hb = __float2bfloat16(hn);
    ah[idx] = hb;
    al[idx] = __float2bfloat16(hn - __bfloat162float(hb));
}

// ---------------- decoder head: h2n + mix + relu + pos ----------------
__global__ void h2n_pos(const float* __restrict__ h,
                        const float* __restrict__ h2nW, const float* __restrict__ h2nB,
                        const float* __restrict__ mixW, const float* __restrict__ mixB,
                        const float* __restrict__ base,
                        float* __restrict__ out_rel, float* __restrict__ out_pos) {
    int row = blockIdx.x;
    int tid = threadIdx.x;
    int warp = tid >> 5, lane = tid & 31;
    __shared__ float sn[5];

    if (warp < 5) {
        const float* hr = h + (size_t)row * HH;
        const float* wr = h2nW + warp * HH;
        float s = 0.0f;
        for (int i = lane; i < HH; i += 32) s = fmaf(hr[i], wr[i], s);
        #pragma unroll
        for (int o = 16; o > 0; o >>= 1) s += __shfl_down_sync(0xffffffffu, s, o);
        if (lane == 0) {
            float raw = s + h2nB[warp];
            float val;
            if (warp < 2) {
                val = raw;
            } else if (warp < 4) {
                float sp = raw > 0.0f ? raw + log1pf(expf(-raw)) : log1pf(expf(raw));
                val = 0.01f + 0.2f * sp;
            } else {
                val = 0.7f * tanhf(raw);
            }
            sn[warp] = val;
            out_rel[(size_t)row * 5 + warp] = val;
        }
    }
    __syncthreads();
    if (tid < DD) {
        float acc = mixB[tid];
        #pragma unroll
        for (int c = 0; c < 5; c++) acc = fmaf(sn[c], mixW[tid * 5 + c], acc);
        acc = acc > 0.0f ? acc : 0.0f;
        out_pos[(size_t)row * DD + tid] = base[(size_t)row * DD + tid] + acc;
    }
}

// ---------------- host orchestration ----------------
extern "C" void kernel_launch(void* const* d_in, const int* in_sizes, int n_in,
                              void* d_out, int out_size) {
    const float* observed = (const float*)d_in[0];
    const float* emb_W    = (const float*)d_in[1];
    const float* emb_b    = (const float*)d_in[2];
    const float* e1_Wih   = (const float*)d_in[3];
    const float* e1_Whh   = (const float*)d_in[4];
    const float* e1_bih   = (const float*)d_in[5];
    const float* e1_bhh   = (const float*)d_in[6];
    const float* e2_Wih   = (const float*)d_in[7];
    const float* e2_Whh   = (const float*)d_in[8];
    const float* e2_bih   = (const float*)d_in[9];
    const float* e2_bhh   = (const float*)d_in[10];
    const float* dec_Wih  = (const float*)d_in[11];
    const float* dec_Whh  = (const float*)d_in[12];
    const float* dec_bih  = (const float*)d_in[13];
    const float* dec_bhh  = (const float*)d_in[14];
    const float* h2n_W    = (const float*)d_in[15];
    const float* h2n_b    = (const float*)d_in[16];
    const float* mix_W    = (const float*)d_in[17];
    const float* mix_b    = (const float*)d_in[18];
    float* out = (float*)d_out;

    float *M1, *M2, *Md, *b1, *b2, *bd, *C2, *G, *h;
    __nv_bfloat16 *Bh1, *Bl1, *Bh2, *Bl2, *Bhd, *Bld, *Bh2x, *Bl2x, *Ah, *Al;
    cudaGetSymbolAddress((void**)&M1,  g_M1);
    cudaGetSymbolAddress((void**)&M2,  g_M2);
    cudaGetSymbolAddress((void**)&Md,  g_Md);
    cudaGetSymbolAddress((void**)&b1,  g_b1);
    cudaGetSymbolAddress((void**)&b2,  g_b2);
    cudaGetSymbolAddress((void**)&bd,  g_bd);
    cudaGetSymbolAddress((void**)&Bh1, g_Bh1);
    cudaGetSymbolAddress((void**)&Bl1, g_Bl1);
    cudaGetSymbolAddress((void**)&Bh2, g_Bh2);
    cudaGetSymbolAddress((void**)&Bl2, g_Bl2);
    cudaGetSymbolAddress((void**)&Bhd, g_Bhd);
    cudaGetSymbolAddress((void**)&Bld, g_Bld);
    cudaGetSymbolAddress((void**)&Bh2x,g_Bh2x);
    cudaGetSymbolAddress((void**)&Bl2x,g_Bl2x);
    cudaGetSymbolAddress((void**)&Ah,  g_Ah);
    cudaGetSymbolAddress((void**)&Al,  g_Al);
    cudaGetSymbolAddress((void**)&C2,  g_C2);
    cudaGetSymbolAddress((void**)&G,   g_G);
    cudaGetSymbolAddress((void**)&h,   g_h);

    cudaFuncSetAttribute(gemm_tc, cudaFuncAttributeMaxDynamicSharedMemorySize, GEMM_SMEM);

    const int ND = NB * DD;           // 32768
    const int NH = NB * HH;           // 1572864
    float* rel_out  = out;                          // (12, 2048, 5)
    float* pred_out = out + (size_t)NPRED * NB * 5; // (12, 2048, 16)

    dim3 gemmGrid(G3 / 256, NB / 128);   // (9, 16) = 144 CTAs = 1 wave
    dim3 gruGrid(HH / 256, NB);          // (3, 2048)
    const int WELEM = G3 * HH;

    // ---- one-time prep (per call; deterministic) ----
    prep_combined<<<(G3 + 255) / 256, 256>>>(e1_Wih,  EE,      e1_bih,  emb_W, emb_b, M1, b1);
    prep_combined<<<(G3 + 255) / 256, 256>>>(e2_Wih,  EE + HH, e2_bih,  emb_W, emb_b, M2, b2);
    prep_combined<<<(G3 + 255) / 256, 256>>>(dec_Wih, EE,      dec_bih, emb_W, emb_b, Md, bd);

    conv_bf16<<<(WELEM + 255) / 256, 256>>>(e1_Whh,  HH,      0,  Bh1,  Bl1);
    conv_bf16<<<(WELEM + 255) / 256, 256>>>(e2_Whh,  HH,      0,  Bh2,  Bl2);
    conv_bf16<<<(WELEM + 255) / 256, 256>>>(dec_Whh, HH,      0,  Bhd,  Bld);
    conv_bf16<<<(WELEM + 255) / 256, 256>>>(e2_Wih,  EE + HH, EE, Bh2x, Bl2x);

    zero_kernel<<<(NH + 255) / 256, 256>>>(h, NH);

    // ---- encoder 1: backward velocities vel_b[t] = obs[7-t] - obs[6-t] ----
    for (int t = 0; t < TT - 1; t++) {
        const float* pa = observed + (size_t)(7 - t) * ND;
        const float* pb = observed + (size_t)(6 - t) * ND;
        const float* Gp = nullptr;
        if (t > 0) {   // t==0: h==0 -> gh==0
            gemm_tc<<<gemmGrid, 256, GEMM_SMEM>>>(Ah, Al, Bh1, Bl1, G);
            Gp = G;
        }
        gru_update<<<gruGrid, 256>>>(M1, b1, e1_bhh, nullptr, Gp, pa, pb, h, Ah, Al);
    }

    // constant enc2 input contribution: C2 = h_inv @ e2_Wih[:,256:]^T
    // (Ah/Al currently hold the split of h_inv)
    gemm_tc<<<gemmGrid, 256, GEMM_SMEM>>>(Ah, Al, Bh2x, Bl2x, C2);

    zero_kernel<<<(NH + 255) / 256, 256>>>(h, NH);

    // ---- encoder 2: forward velocities vel_f[t] = obs[t+1] - obs[t] ----
    for (int t = 0; t < TT - 1; t++) {
        const float* pa = observed + (size_t)(t + 1) * ND;
        const float* pb = observed + (size_t)t * ND;
        const float* Gp = nullptr;
        if (t > 0) {
            gemm_tc<<<gemmGrid, 256, GEMM_SMEM>>>(Ah, Al, Bh2, Bl2, G);
            Gp = G;
        }
        gru_update<<<gruGrid, 256>>>(M2, b2, e2_bhh, C2, Gp, pa, pb, h, Ah, Al);
    }

    // ---- decoder: 12 autoregressive steps ----
    for (int k = 0; k < NPRED; k++) {
        const float *pa, *pb;
        if (k == 0) {
            pa = observed + (size_t)7 * ND;
            pb = observed + (size_t)6 * ND;
        } else if (k == 1) {
            pa = pred_out;                        // p0
            pb = observed + (size_t)7 * ND;
        } else {
            pa = pred_out + (size_t)(k - 1) * ND; // p_{k-1}
            pb = pred_out + (size_t)(k - 2) * ND; // p_{k-2}
        }
        gemm_tc<<<gemmGrid, 256, GEMM_SMEM>>>(Ah, Al, Bhd, Bld, G);
        gru_update<<<gruGrid, 256>>>(Md, bd, dec_bhh, nullptr, G, pa, pb, h, Ah, Al);
        h2n_pos<<<NB, 160>>>(h, h2n_W, h2n_b, mix_W, mix_b, pa,
                             rel_out + (size_t)k * NB * 5,
                             pred_out + (size_t)k * ND);
    }
}